// round 2
// baseline (speedup 1.0000x reference)
#include <cuda_runtime.h>
#include <cstdint>

#define N_NODES 50000
#define D_IN 128
#define D_H 256
#define BM 64
#define BN 64
#define BK 16

// ---------------- scratch (device globals: no allocs allowed) ----------------
__device__ __align__(16) float g_agg0[(size_t)N_NODES * D_IN];  // mean-agg of x
__device__ __align__(16) float g_h0  [(size_t)N_NODES * D_H];   // relu(layer0)
__device__ __align__(16) float g_agg1[(size_t)N_NODES * D_H];   // mean-agg of h0
__device__ __align__(16) float g_h1  [(size_t)N_NODES * D_H];   // relu(layer1)
__device__ __align__(16) float g_p2  [(size_t)N_NODES * D_IN];  // h1 @ W_l2 (project-first)
__device__ int   g_cnt[N_NODES];
__device__ float g_inv[N_NODES];
__device__ int   g_i64;   // 1 if edge_index is actually int64, 0 if int32

// ---------------- dtype detection ----------------
// Reference says jnp.int64, but JAX without x64 silently produces int32.
// If the buffer really is int64 with node ids < 2^31, every odd 32-bit word
// of the first 256 entries is 0. For genuine int32 ids in [0, 50000) the
// odds of that are ~(1/50000)^256 == 0.
__global__ void detect_kernel(const int* __restrict__ ei) {
    if (threadIdx.x == 0 && blockIdx.x == 0) {
        int all0 = 1;
        for (int i = 0; i < 256; i++)
            if (ei[2 * i + 1] != 0) { all0 = 0; break; }
        g_i64 = all0;
    }
}

__device__ __forceinline__ int load_src(const int* ei, int i, int E, int i64) {
    return i64 ? ei[2 * i] : ei[i];
}
__device__ __forceinline__ int load_dst(const int* ei, int i, int E, int i64) {
    return i64 ? ei[2 * (E + i)] : ei[E + i];
}

// ---------------- init ----------------
__global__ void zero_all_kernel() {
    int stride = gridDim.x * blockDim.x;
    int tid = blockIdx.x * blockDim.x + threadIdx.x;
    for (int i = tid; i < N_NODES * D_IN; i += stride) g_agg0[i] = 0.f;
    for (int i = tid; i < N_NODES * D_H;  i += stride) g_agg1[i] = 0.f;
    for (int i = tid; i < N_NODES;        i += stride) g_cnt[i] = 0;
}

__global__ void count_kernel(const int* __restrict__ ei, int E) {
    int i = blockIdx.x * blockDim.x + threadIdx.x;
    if (i < E) {
        int d = load_dst(ei, i, E, g_i64);
        atomicAdd(&g_cnt[d], 1);
    }
}

__global__ void inv_kernel() {
    int i = blockIdx.x * blockDim.x + threadIdx.x;
    if (i < N_NODES) {
        int c = g_cnt[i];
        g_inv[i] = 1.0f / (float)(c > 0 ? c : 1);
    }
}

// ---------------- edge scatter (mean folded in via inv_cnt[dst]) ----------------
__device__ __forceinline__ void red_add_v4(float* addr, float a, float b, float c, float d) {
    asm volatile("red.global.add.v4.f32 [%0], {%1,%2,%3,%4};"
                 :: "l"(addr), "f"(a), "f"(b), "f"(c), "f"(d) : "memory");
}

// one warp per edge; lane l handles a float4 slice of the feature row
template<int D>
__global__ void scatter_kernel(const float* __restrict__ feat,
                               const int* __restrict__ ei,
                               float* __restrict__ out, int E) {
    int gw = (int)((blockIdx.x * (unsigned)blockDim.x + threadIdx.x) >> 5);
    if (gw >= E) return;
    int lane = threadIdx.x & 31;
    int i64 = g_i64;
    int s = load_src(ei, gw, E, i64);
    int d = load_dst(ei, gw, E, i64);
    float w = __ldg(&g_inv[d]);
    const float4* in4 = reinterpret_cast<const float4*>(feat) + (size_t)s * (D / 4);
    float* o = out + (size_t)d * D;
#pragma unroll
    for (int i = 0; i < D / 128; i++) {
        int idx = lane + i * 32;
        float4 v = __ldg(&in4[idx]);
        red_add_v4(o + idx * 4, v.x * w, v.y * w, v.z * w, v.w * w);
    }
}

// ---------------- fused dual-source GEMM: C = A1@W1 (+ A2@W2) (+ bias) (relu?) ----------------
__global__ void __launch_bounds__(256) gemm2_kernel(
    const float* __restrict__ A1, const float* __restrict__ W1,
    const float* __restrict__ A2, const float* __restrict__ W2,
    const float* __restrict__ bias, float* __restrict__ C,
    int N, int K, int M, int do_relu)
{
    __shared__ float sA1[BK][BM + 4];
    __shared__ float sW1[BK][BN + 4];
    __shared__ float sA2[BK][BM + 4];
    __shared__ float sW2[BK][BN + 4];

    const bool dual = (A2 != nullptr);
    const int tid = threadIdx.x;
    const int tx = tid & 15;
    const int ty = tid >> 4;
    const int row0 = blockIdx.y * BM;
    const int col0 = blockIdx.x * BN;

    // A tile: 64 rows x 16 k; each thread loads 4 consecutive k of one row
    const int la_m = tid >> 2;
    const int la_k = (tid & 3) * 4;
    // W tile: 16 k x 64 cols; each thread loads 4 consecutive cols of one k
    const int lw_k = tid >> 4;
    const int lw_c = (tid & 15) * 4;

    float acc[4][4];
#pragma unroll
    for (int i = 0; i < 4; i++)
#pragma unroll
        for (int j = 0; j < 4; j++) acc[i][j] = 0.f;

    for (int k0 = 0; k0 < K; k0 += BK) {
        int gr = row0 + la_m;
        float4 v1 = make_float4(0.f, 0.f, 0.f, 0.f);
        float4 v2 = make_float4(0.f, 0.f, 0.f, 0.f);
        if (gr < N) {
            v1 = *reinterpret_cast<const float4*>(A1 + (size_t)gr * K + k0 + la_k);
            if (dual)
                v2 = *reinterpret_cast<const float4*>(A2 + (size_t)gr * K + k0 + la_k);
        }
        sA1[la_k + 0][la_m] = v1.x; sA1[la_k + 1][la_m] = v1.y;
        sA1[la_k + 2][la_m] = v1.z; sA1[la_k + 3][la_m] = v1.w;
        if (dual) {
            sA2[la_k + 0][la_m] = v2.x; sA2[la_k + 1][la_m] = v2.y;
            sA2[la_k + 2][la_m] = v2.z; sA2[la_k + 3][la_m] = v2.w;
        }
        {
            const float4 w1 = *reinterpret_cast<const float4*>(
                W1 + (size_t)(k0 + lw_k) * M + col0 + lw_c);
            *reinterpret_cast<float4*>(&sW1[lw_k][lw_c]) = w1;
            if (dual) {
                const float4 w2 = *reinterpret_cast<const float4*>(
                    W2 + (size_t)(k0 + lw_k) * M + col0 + lw_c);
                *reinterpret_cast<float4*>(&sW2[lw_k][lw_c]) = w2;
            }
        }
        __syncthreads();

#pragma unroll
        for (int k = 0; k < BK; k++) {
            float4 a = *reinterpret_cast<const float4*>(&sA1[k][ty * 4]);
            float4 w = *reinterpret_cast<const float4*>(&sW1[k][tx * 4]);
            acc[0][0] += a.x * w.x; acc[0][1] += a.x * w.y; acc[0][2] += a.x * w.z; acc[0][3] += a.x * w.w;
            acc[1][0] += a.y * w.x; acc[1][1] += a.y * w.y; acc[1][2] += a.y * w.z; acc[1][3] += a.y * w.w;
            acc[2][0] += a.z * w.x; acc[2][1] += a.z * w.y; acc[2][2] += a.z * w.z; acc[2][3] += a.z * w.w;
            acc[3][0] += a.w * w.x; acc[3][1] += a.w * w.y; acc[3][2] += a.w * w.z; acc[3][3] += a.w * w.w;
            if (dual) {
                float4 a2 = *reinterpret_cast<const float4*>(&sA2[k][ty * 4]);
                float4 w2 = *reinterpret_cast<const float4*>(&sW2[k][tx * 4]);
                acc[0][0] += a2.x * w2.x; acc[0][1] += a2.x * w2.y; acc[0][2] += a2.x * w2.z; acc[0][3] += a2.x * w2.w;
                acc[1][0] += a2.y * w2.x; acc[1][1] += a2.y * w2.y; acc[1][2] += a2.y * w2.z; acc[1][3] += a2.y * w2.w;
                acc[2][0] += a2.z * w2.x; acc[2][1] += a2.z * w2.y; acc[2][2] += a2.z * w2.z; acc[2][3] += a2.z * w2.w;
                acc[3][0] += a2.w * w2.x; acc[3][1] += a2.w * w2.y; acc[3][2] += a2.w * w2.z; acc[3][3] += a2.w * w2.w;
            }
        }
        __syncthreads();
    }

    float4 bv = make_float4(0.f, 0.f, 0.f, 0.f);
    if (bias) bv = *reinterpret_cast<const float4*>(bias + col0 + tx * 4);
#pragma unroll
    for (int i = 0; i < 4; i++) {
        int r = row0 + ty * 4 + i;
        if (r < N) {
            float4 o;
            o.x = acc[i][0] + bv.x; o.y = acc[i][1] + bv.y;
            o.z = acc[i][2] + bv.z; o.w = acc[i][3] + bv.w;
            if (do_relu) {
                o.x = fmaxf(o.x, 0.f); o.y = fmaxf(o.y, 0.f);
                o.z = fmaxf(o.z, 0.f); o.w = fmaxf(o.w, 0.f);
            }
            *reinterpret_cast<float4*>(C + (size_t)r * M + col0 + tx * 4) = o;
        }
    }
}

// ---------------- launch ----------------
extern "C" void kernel_launch(void* const* d_in, const int* in_sizes, int n_in,
                              void* d_out, int out_size) {
    const float* x   = (const float*)d_in[0];
    const int*   ei  = (const int*)d_in[1];   // int32 in practice (JAX x64 off); int64 handled via g_i64
    const float* Wl0 = (const float*)d_in[2];
    const float* b0  = (const float*)d_in[3];
    const float* Wr0 = (const float*)d_in[4];
    const float* Wl1 = (const float*)d_in[5];
    const float* b1  = (const float*)d_in[6];
    const float* Wr1 = (const float*)d_in[7];
    const float* Wl2 = (const float*)d_in[8];
    const float* b2  = (const float*)d_in[9];
    const float* Wr2 = (const float*)d_in[10];
    float* out = (float*)d_out;

    const int E = in_sizes[1] / 2;            // edge_index is (2, E)

    float *agg0, *h0, *agg1, *h1, *p2;
    cudaGetSymbolAddress((void**)&agg0, g_agg0);
    cudaGetSymbolAddress((void**)&h0,   g_h0);
    cudaGetSymbolAddress((void**)&agg1, g_agg1);
    cudaGetSymbolAddress((void**)&h1,   g_h1);
    cudaGetSymbolAddress((void**)&p2,   g_p2);

    detect_kernel<<<1, 32>>>(ei);
    zero_all_kernel<<<2048, 256>>>();
    count_kernel<<<(E + 255) / 256, 256>>>(ei, E);
    inv_kernel<<<(N_NODES + 255) / 256, 256>>>();

    const int sblocks = (E + 7) / 8;          // 8 warps (edges) per 256-thread block
    dim3 gH(D_H / BN, (N_NODES + BM - 1) / BM);
    dim3 gO(D_IN / BN, (N_NODES + BM - 1) / BM);

    // layer 0: aggregate-first (128 dims), fused dual GEMM + bias + relu
    scatter_kernel<D_IN><<<sblocks, 256>>>(x, ei, agg0, E);
    gemm2_kernel<<<gH, 256>>>(agg0, Wl0, x, Wr0, b0, h0, N_NODES, D_IN, D_H, 1);

    // layer 1: aggregate-first (256 dims)
    scatter_kernel<D_H><<<sblocks, 256>>>(h0, ei, agg1, E);
    gemm2_kernel<<<gH, 256>>>(agg1, Wl1, h0, Wr1, b1, h1, N_NODES, D_H, D_H, 1);

    // layer 2: project-first so the edge aggregation runs in 128 dims not 256
    gemm2_kernel<<<gO, 256>>>(h1, Wl2, nullptr, nullptr, nullptr, p2, N_NODES, D_H, D_IN, 0);
    gemm2_kernel<<<gO, 256>>>(h1, Wr2, nullptr, nullptr, b2, out, N_NODES, D_H, D_IN, 0);
    scatter_kernel<D_IN><<<sblocks, 256>>>(p2, ei, out, E);
}

// round 3
// speedup vs baseline: 1.3683x; 1.3683x over previous
#include <cuda_runtime.h>
#include <cuda_bf16.h>
#include <cstdint>

#define N_NODES 50000
#define D_IN 128
#define D_H 256

// ---------------- scratch (device globals: no allocs allowed) ----------------
__device__ __align__(16) float g_agg0[(size_t)N_NODES * D_IN];  // mean-agg of x
__device__ __align__(16) float g_h0  [(size_t)N_NODES * D_H];   // relu(layer0)
__device__ __align__(16) float g_agg1[(size_t)N_NODES * D_H];   // mean-agg of h0
__device__ __align__(16) float g_h1  [(size_t)N_NODES * D_H];   // relu(layer1)
__device__ __align__(16) float g_p2  [(size_t)N_NODES * D_IN];  // h1 @ W_l2 (project-first)
__device__ int   g_cnt[N_NODES];
__device__ float g_inv[N_NODES];
__device__ int   g_i64;   // 1 if edge_index is actually int64, 0 if int32

// ---------------- dtype detection (int64 vs silently-downcast int32) --------
__global__ void detect_kernel(const int* __restrict__ ei) {
    if (threadIdx.x == 0 && blockIdx.x == 0) {
        int all0 = 1;
        for (int i = 0; i < 256; i++)
            if (ei[2 * i + 1] != 0) { all0 = 0; break; }
        g_i64 = all0;
    }
}

__device__ __forceinline__ int load_src(const int* ei, int i, int E, int i64) {
    return i64 ? ei[2 * i] : ei[i];
}
__device__ __forceinline__ int load_dst(const int* ei, int i, int E, int i64) {
    return i64 ? ei[2 * (E + i)] : ei[E + i];
}

// ---------------- init ----------------
__global__ void zero_all_kernel() {
    int stride = gridDim.x * blockDim.x;
    int tid = blockIdx.x * blockDim.x + threadIdx.x;
    for (int i = tid; i < N_NODES * D_IN; i += stride) g_agg0[i] = 0.f;
    for (int i = tid; i < N_NODES * D_H;  i += stride) g_agg1[i] = 0.f;
    for (int i = tid; i < N_NODES;        i += stride) g_cnt[i] = 0;
}

__global__ void count_kernel(const int* __restrict__ ei, int E) {
    int i = blockIdx.x * blockDim.x + threadIdx.x;
    if (i < E) {
        int d = load_dst(ei, i, E, g_i64);
        atomicAdd(&g_cnt[d], 1);
    }
}

__global__ void inv_kernel() {
    int i = blockIdx.x * blockDim.x + threadIdx.x;
    if (i < N_NODES) {
        int c = g_cnt[i];
        g_inv[i] = 1.0f / (float)(c > 0 ? c : 1);
    }
}

// ---------------- edge scatter (mean folded in via inv_cnt[dst]) ----------------
__device__ __forceinline__ void red_add_v4(float* addr, float a, float b, float c, float d) {
    asm volatile("red.global.add.v4.f32 [%0], {%1,%2,%3,%4};"
                 :: "l"(addr), "f"(a), "f"(b), "f"(c), "f"(d) : "memory");
}

// one warp per edge; lane l handles a float4 slice of the feature row
template<int D>
__global__ void scatter_kernel(const float* __restrict__ feat,
                               const int* __restrict__ ei,
                               float* __restrict__ out, int E) {
    int gw = (int)((blockIdx.x * (unsigned)blockDim.x + threadIdx.x) >> 5);
    if (gw >= E) return;
    int lane = threadIdx.x & 31;
    int i64 = g_i64;
    int s = load_src(ei, gw, E, i64);
    int d = load_dst(ei, gw, E, i64);
    float w = __ldg(&g_inv[d]);
    const float4* in4 = reinterpret_cast<const float4*>(feat) + (size_t)s * (D / 4);
    float* o = out + (size_t)d * D;
#pragma unroll
    for (int i = 0; i < D / 128; i++) {
        int idx = lane + i * 32;
        float4 v = __ldg(&in4[idx]);
        red_add_v4(o + idx * 4, v.x * w, v.y * w, v.z * w, v.w * w);
    }
}

// ---------------- tensor-core GEMM helpers ----------------
__device__ __forceinline__ uint32_t smem_u32(const void* p) {
    return (uint32_t)__cvta_generic_to_shared(p);
}
__device__ __forceinline__ void ldsm_x4(uint32_t* r, uint32_t a) {
    asm volatile("ldmatrix.sync.aligned.m8n8.x4.shared.b16 {%0,%1,%2,%3}, [%4];"
                 : "=r"(r[0]), "=r"(r[1]), "=r"(r[2]), "=r"(r[3]) : "r"(a));
}
__device__ __forceinline__ void ldsm_x4_t(uint32_t* r, uint32_t a) {
    asm volatile("ldmatrix.sync.aligned.m8n8.x4.trans.shared.b16 {%0,%1,%2,%3}, [%4];"
                 : "=r"(r[0]), "=r"(r[1]), "=r"(r[2]), "=r"(r[3]) : "r"(a));
}
__device__ __forceinline__ void mma16816(float* c, const uint32_t* a, const uint32_t* b) {
    asm volatile("mma.sync.aligned.m16n8k16.row.col.f32.bf16.bf16.f32 "
                 "{%0,%1,%2,%3}, {%4,%5,%6,%7}, {%8,%9}, {%0,%1,%2,%3};"
                 : "+f"(c[0]), "+f"(c[1]), "+f"(c[2]), "+f"(c[3])
                 : "r"(a[0]), "r"(a[1]), "r"(a[2]), "r"(a[3]),
                   "r"(b[0]), "r"(b[1]));
}

// ---- fused dual-source GEMM on tensor cores, fp32 via 3-term bf16 split ----
// C[N x M] = A1@W1 (+ A2@W2) (+ bias) (relu?)
// block tile 128x128, BK=32, 8 warps as 2(m) x 4(n); warp tile 64x32.
__global__ void __launch_bounds__(256) gemm2_tc(
    const float* __restrict__ A1, const float* __restrict__ W1,
    const float* __restrict__ A2, const float* __restrict__ W2,
    const float* __restrict__ bias, float* __restrict__ C,
    int Nrows, int K, int M, int do_relu)
{
    __shared__ __align__(16) __nv_bfloat16 sA[2][128][40];   // [hi/lo][m][k], pad 8
    __shared__ __align__(16) __nv_bfloat16 sW[2][32][136];   // [hi/lo][k][n], pad 8

    const int tid  = threadIdx.x;
    const int lane = tid & 31;
    const int warp = tid >> 5;
    const int wm = warp & 1;          // 0..1 -> 64-row half
    const int wn = warp >> 1;         // 0..3 -> 32-col strip
    const int row0 = blockIdx.y * 128;
    const int col0 = blockIdx.x * 128;

    float acc[4][4][4];               // [m16 tile][n8 tile][frag]
#pragma unroll
    for (int a = 0; a < 4; a++)
#pragma unroll
        for (int b = 0; b < 4; b++)
#pragma unroll
            for (int c = 0; c < 4; c++) acc[a][b][c] = 0.f;

    const int nsrc = (A2 != nullptr) ? 2 : 1;
    for (int s = 0; s < nsrc; s++) {
        const float* A = s ? A2 : A1;
        const float* W = s ? W2 : W1;
        for (int k0 = 0; k0 < K; k0 += 32) {
            // ---- load A tile (128 x 32 fp32), split to hi/lo bf16 ----
#pragma unroll
            for (int i = 0; i < 4; i++) {
                int f = tid + 256 * i;            // 0..1023 float4 slots
                int r = f >> 3;                   // 128 rows
                int c4 = (f & 7) * 4;             // col within 32
                float4 v = make_float4(0.f, 0.f, 0.f, 0.f);
                int gr = row0 + r;
                if (gr < Nrows)
                    v = *reinterpret_cast<const float4*>(A + (size_t)gr * K + k0 + c4);
                float vv[4] = {v.x, v.y, v.z, v.w};
#pragma unroll
                for (int j = 0; j < 4; j++) {
                    __nv_bfloat16 h = __float2bfloat16(vv[j]);
                    sA[0][r][c4 + j] = h;
                    sA[1][r][c4 + j] = __float2bfloat16(vv[j] - __bfloat162float(h));
                }
            }
            // ---- load W tile (32 x 128 fp32), split to hi/lo bf16 ----
#pragma unroll
            for (int i = 0; i < 4; i++) {
                int f = tid + 256 * i;
                int r = f >> 5;                   // 32 k-rows
                int c4 = (f & 31) * 4;            // col within 128
                float4 v = *reinterpret_cast<const float4*>(
                    W + (size_t)(k0 + r) * M + col0 + c4);
                float vv[4] = {v.x, v.y, v.z, v.w};
#pragma unroll
                for (int j = 0; j < 4; j++) {
                    __nv_bfloat16 h = __float2bfloat16(vv[j]);
                    sW[0][r][c4 + j] = h;
                    sW[1][r][c4 + j] = __float2bfloat16(vv[j] - __bfloat162float(h));
                }
            }
            __syncthreads();

#pragma unroll
            for (int ks = 0; ks < 32; ks += 16) {
                uint32_t ahi[4][4], alo[4][4];
#pragma unroll
                for (int mt = 0; mt < 4; mt++) {
                    int r = wm * 64 + mt * 16 + (lane & 15);
                    int c = ks + (lane >> 4) * 8;
                    ldsm_x4(ahi[mt], smem_u32(&sA[0][r][c]));
                    ldsm_x4(alo[mt], smem_u32(&sA[1][r][c]));
                }
#pragma unroll
                for (int nt = 0; nt < 2; nt++) {      // two n16 chunks
                    int kr = ks + (lane & 15);
                    int c  = wn * 32 + nt * 16 + (lane >> 4) * 8;
                    uint32_t bhi[4], blo[4];          // {t0b0,t0b1,t1b0,t1b1}
                    ldsm_x4_t(bhi, smem_u32(&sW[0][kr][c]));
                    ldsm_x4_t(blo, smem_u32(&sW[1][kr][c]));
#pragma unroll
                    for (int mt = 0; mt < 4; mt++) {
#pragma unroll
                        for (int h = 0; h < 2; h++) { // n8 halves
                            float* cc = acc[mt][nt * 2 + h];
                            mma16816(cc, ahi[mt], &bhi[h * 2]);
                            mma16816(cc, alo[mt], &bhi[h * 2]);
                            mma16816(cc, ahi[mt], &blo[h * 2]);
                        }
                    }
                }
            }
            __syncthreads();
        }
    }

    // ---- epilogue: bias + relu, direct global store ----
#pragma unroll
    for (int mt = 0; mt < 4; mt++) {
#pragma unroll
        for (int nt = 0; nt < 4; nt++) {
            int rg = row0 + wm * 64 + mt * 16 + (lane >> 2);
            int cg = col0 + wn * 32 + nt * 8 + (lane & 3) * 2;
            float b0v = 0.f, b1v = 0.f;
            if (bias) { b0v = bias[cg]; b1v = bias[cg + 1]; }
            float o0 = acc[mt][nt][0] + b0v;
            float o1 = acc[mt][nt][1] + b1v;
            float o2 = acc[mt][nt][2] + b0v;
            float o3 = acc[mt][nt][3] + b1v;
            if (do_relu) {
                o0 = fmaxf(o0, 0.f); o1 = fmaxf(o1, 0.f);
                o2 = fmaxf(o2, 0.f); o3 = fmaxf(o3, 0.f);
            }
            if (rg < Nrows) {
                float2 t = make_float2(o0, o1);
                *reinterpret_cast<float2*>(C + (size_t)rg * M + cg) = t;
            }
            if (rg + 8 < Nrows) {
                float2 t = make_float2(o2, o3);
                *reinterpret_cast<float2*>(C + (size_t)(rg + 8) * M + cg) = t;
            }
        }
    }
}

// ---------------- launch ----------------
extern "C" void kernel_launch(void* const* d_in, const int* in_sizes, int n_in,
                              void* d_out, int out_size) {
    const float* x   = (const float*)d_in[0];
    const int*   ei  = (const int*)d_in[1];   // int32 in practice; int64 handled via g_i64
    const float* Wl0 = (const float*)d_in[2];
    const float* b0  = (const float*)d_in[3];
    const float* Wr0 = (const float*)d_in[4];
    const float* Wl1 = (const float*)d_in[5];
    const float* b1  = (const float*)d_in[6];
    const float* Wr1 = (const float*)d_in[7];
    const float* Wl2 = (const float*)d_in[8];
    const float* b2  = (const float*)d_in[9];
    const float* Wr2 = (const float*)d_in[10];
    float* out = (float*)d_out;

    const int E = in_sizes[1] / 2;            // edge_index is (2, E)

    float *agg0, *h0, *agg1, *h1, *p2;
    cudaGetSymbolAddress((void**)&agg0, g_agg0);
    cudaGetSymbolAddress((void**)&h0,   g_h0);
    cudaGetSymbolAddress((void**)&agg1, g_agg1);
    cudaGetSymbolAddress((void**)&h1,   g_h1);
    cudaGetSymbolAddress((void**)&p2,   g_p2);

    detect_kernel<<<1, 32>>>(ei);
    zero_all_kernel<<<2048, 256>>>();
    count_kernel<<<(E + 255) / 256, 256>>>(ei, E);
    inv_kernel<<<(N_NODES + 255) / 256, 256>>>();

    const int sblocks = (E + 7) / 8;          // 8 warps (edges) per 256-thread block
    const int gy = (N_NODES + 127) / 128;     // 391
    dim3 gH(D_H / 128, gy);                   // M=256 -> x=2
    dim3 gO(D_IN / 128, gy);                  // M=128 -> x=1

    // layer 0: aggregate-first (128 dims), fused dual GEMM + bias + relu
    scatter_kernel<D_IN><<<sblocks, 256>>>(x, ei, agg0, E);
    gemm2_tc<<<gH, 256>>>(agg0, Wl0, x, Wr0, b0, h0, N_NODES, D_IN, D_H, 1);

    // layer 1: aggregate-first (256 dims)
    scatter_kernel<D_H><<<sblocks, 256>>>(h0, ei, agg1, E);
    gemm2_tc<<<gH, 256>>>(agg1, Wl1, h0, Wr1, b1, h1, N_NODES, D_H, D_H, 1);

    // layer 2: project-first so the edge aggregation runs in 128 dims not 256
    gemm2_tc<<<gO, 256>>>(h1, Wl2, nullptr, nullptr, nullptr, p2, N_NODES, D_H, D_IN, 0);
    gemm2_tc<<<gO, 256>>>(h1, Wr2, nullptr, nullptr, b2, out, N_NODES, D_H, D_IN, 0);
    scatter_kernel<D_IN><<<sblocks, 256>>>(p2, ei, out, E);
}

// round 4
// speedup vs baseline: 1.5366x; 1.1230x over previous
#include <cuda_runtime.h>
#include <cuda_bf16.h>
#include <cstdint>

#define N_NODES 50000
#define D_IN 128
#define D_H 256

typedef __nv_bfloat16 bf16;
typedef __nv_bfloat162 bf162;

// ---------------- scratch (device globals: no allocs allowed) ----------------
__device__ __align__(16) float g_agg0[(size_t)N_NODES * D_IN];
__device__ __align__(16) float g_agg1[(size_t)N_NODES * D_H];
__device__ __align__(16) float g_p2  [(size_t)N_NODES * D_IN];
__device__ __align__(16) bf16  g_xhi [(size_t)N_NODES * D_IN];
__device__ __align__(16) bf16  g_xlo [(size_t)N_NODES * D_IN];
__device__ __align__(16) bf16  g_h0hi[(size_t)N_NODES * D_H];
__device__ __align__(16) bf16  g_h0lo[(size_t)N_NODES * D_H];
__device__ __align__(16) bf16  g_h1hi[(size_t)N_NODES * D_H];
__device__ __align__(16) bf16  g_h1lo[(size_t)N_NODES * D_H];
__device__ __align__(16) bf16  g_whi [262144];
__device__ __align__(16) bf16  g_wlo [262144];
__device__ int   g_cnt[N_NODES];
__device__ float g_inv[N_NODES];
__device__ int   g_i64;

// weight offsets inside g_whi/g_wlo (elements)
#define OFF_WL0 0
#define OFF_WR0 32768
#define OFF_WL1 65536
#define OFF_WR1 131072
#define OFF_WL2 196608
#define OFF_WR2 229376

// ---------------- dtype detection (int64 vs silently-downcast int32) --------
__global__ void detect_kernel(const int* __restrict__ ei) {
    if (threadIdx.x == 0 && blockIdx.x == 0) {
        int all0 = 1;
        for (int i = 0; i < 256; i++)
            if (ei[2 * i + 1] != 0) { all0 = 0; break; }
        g_i64 = all0;
    }
}
__device__ __forceinline__ int load_src(const int* ei, int i, int E, int i64) {
    return i64 ? ei[2 * i] : ei[i];
}
__device__ __forceinline__ int load_dst(const int* ei, int i, int E, int i64) {
    return i64 ? ei[2 * (E + i)] : ei[E + i];
}

// ---------------- init ----------------
__global__ void zero_all_kernel() {
    int stride = gridDim.x * blockDim.x;
    int tid = blockIdx.x * blockDim.x + threadIdx.x;
    for (int i = tid; i < N_NODES * D_IN; i += stride) g_agg0[i] = 0.f;
    for (int i = tid; i < N_NODES * D_H;  i += stride) g_agg1[i] = 0.f;
    for (int i = tid; i < N_NODES;        i += stride) g_cnt[i] = 0;
}
__global__ void count_kernel(const int* __restrict__ ei, int E) {
    int i = blockIdx.x * blockDim.x + threadIdx.x;
    if (i < E) atomicAdd(&g_cnt[load_dst(ei, i, E, g_i64)], 1);
}
__global__ void inv_kernel() {
    int i = blockIdx.x * blockDim.x + threadIdx.x;
    if (i < N_NODES) {
        int c = g_cnt[i];
        g_inv[i] = 1.0f / (float)(c > 0 ? c : 1);
    }
}

// ---------------- fp32 -> (hi, lo) bf16 split, 4 elems/thread ----------------
__global__ void split4_kernel(const float4* __restrict__ src,
                              bf162* __restrict__ hi, bf162* __restrict__ lo, int n4) {
    int i = blockIdx.x * blockDim.x + threadIdx.x;
    if (i >= n4) return;
    float4 v = src[i];
    bf16 hx = __float2bfloat16(v.x), hy = __float2bfloat16(v.y);
    bf16 hz = __float2bfloat16(v.z), hw = __float2bfloat16(v.w);
    hi[2 * i]     = __halves2bfloat162(hx, hy);
    hi[2 * i + 1] = __halves2bfloat162(hz, hw);
    lo[2 * i]     = __halves2bfloat162(__float2bfloat16(v.x - __bfloat162float(hx)),
                                       __float2bfloat16(v.y - __bfloat162float(hy)));
    lo[2 * i + 1] = __halves2bfloat162(__float2bfloat16(v.z - __bfloat162float(hz)),
                                       __float2bfloat16(v.w - __bfloat162float(hw)));
}

// ---------------- edge scatter (mean folded in via inv_cnt[dst]) ------------
__device__ __forceinline__ void red_add_v4(float* addr, float a, float b, float c, float d) {
    asm volatile("red.global.add.v4.f32 [%0], {%1,%2,%3,%4};"
                 :: "l"(addr), "f"(a), "f"(b), "f"(c), "f"(d) : "memory");
}

// fp32-feature variant: one warp per edge
template<int D>
__global__ void scatter_kernel(const float* __restrict__ feat,
                               const int* __restrict__ ei,
                               float* __restrict__ out, int E) {
    int gw = (int)((blockIdx.x * (unsigned)blockDim.x + threadIdx.x) >> 5);
    if (gw >= E) return;
    int lane = threadIdx.x & 31;
    int i64 = g_i64;
    int s = load_src(ei, gw, E, i64);
    int d = load_dst(ei, gw, E, i64);
    float w = __ldg(&g_inv[d]);
    const float4* in4 = reinterpret_cast<const float4*>(feat) + (size_t)s * (D / 4);
    float* o = out + (size_t)d * D;
#pragma unroll
    for (int i = 0; i < D / 128; i++) {
        int idx = lane + i * 32;
        float4 v = __ldg(&in4[idx]);
        red_add_v4(o + idx * 4, v.x * w, v.y * w, v.z * w, v.w * w);
    }
}

// split-feature variant (reads hi+lo, reconstructs fp32)
template<int D>
__global__ void scatter_split_kernel(const bf16* __restrict__ fhi,
                                     const bf16* __restrict__ flo,
                                     const int* __restrict__ ei,
                                     float* __restrict__ out, int E) {
    int gw = (int)((blockIdx.x * (unsigned)blockDim.x + threadIdx.x) >> 5);
    if (gw >= E) return;
    int lane = threadIdx.x & 31;
    int i64 = g_i64;
    int s = load_src(ei, gw, E, i64);
    int d = load_dst(ei, gw, E, i64);
    float w = __ldg(&g_inv[d]);
    const bf162* h2 = reinterpret_cast<const bf162*>(fhi + (size_t)s * D);
    const bf162* l2 = reinterpret_cast<const bf162*>(flo + (size_t)s * D);
    float* o = out + (size_t)d * D;
#pragma unroll
    for (int i = 0; i < D / 128; i++) {
        int idx = lane + i * 32;       // float4-slot index
        bf162 ha = h2[idx * 2], hb = h2[idx * 2 + 1];
        bf162 la = l2[idx * 2], lb = l2[idx * 2 + 1];
        float vx = __bfloat162float(ha.x) + __bfloat162float(la.x);
        float vy = __bfloat162float(ha.y) + __bfloat162float(la.y);
        float vz = __bfloat162float(hb.x) + __bfloat162float(lb.x);
        float vw = __bfloat162float(hb.y) + __bfloat162float(lb.y);
        red_add_v4(o + idx * 4, vx * w, vy * w, vz * w, vw * w);
    }
}

// ---------------- tensor-core GEMM helpers ----------------
__device__ __forceinline__ uint32_t smem_u32(const void* p) {
    return (uint32_t)__cvta_generic_to_shared(p);
}
__device__ __forceinline__ void ldsm_x4(uint32_t* r, uint32_t a) {
    asm volatile("ldmatrix.sync.aligned.m8n8.x4.shared.b16 {%0,%1,%2,%3}, [%4];"
                 : "=r"(r[0]), "=r"(r[1]), "=r"(r[2]), "=r"(r[3]) : "r"(a));
}
__device__ __forceinline__ void ldsm_x4_t(uint32_t* r, uint32_t a) {
    asm volatile("ldmatrix.sync.aligned.m8n8.x4.trans.shared.b16 {%0,%1,%2,%3}, [%4];"
                 : "=r"(r[0]), "=r"(r[1]), "=r"(r[2]), "=r"(r[3]) : "r"(a));
}
__device__ __forceinline__ void mma16816(float* c, const uint32_t* a, const uint32_t* b) {
    asm volatile("mma.sync.aligned.m16n8k16.row.col.f32.bf16.bf16.f32 "
                 "{%0,%1,%2,%3}, {%4,%5,%6,%7}, {%8,%9}, {%0,%1,%2,%3};"
                 : "+f"(c[0]), "+f"(c[1]), "+f"(c[2]), "+f"(c[3])
                 : "r"(a[0]), "r"(a[1]), "r"(a[2]), "r"(a[3]),
                   "r"(b[0]), "r"(b[1]));
}
__device__ __forceinline__ void cp16(uint32_t dst, const void* src) {
    asm volatile("cp.async.ca.shared.global [%0], [%1], 16;" :: "r"(dst), "l"(src));
}
__device__ __forceinline__ void cp8(uint32_t dst, const void* src) {
    asm volatile("cp.async.ca.shared.global [%0], [%1], 8;" :: "r"(dst), "l"(src));
}
__device__ __forceinline__ void cp_commit() { asm volatile("cp.async.commit_group;"); }
__device__ __forceinline__ void cp_wait0()  { asm volatile("cp.async.wait_group 0;" ::: "memory"); }

// smem stage layout (bytes): A-hi 128x40, A-lo, W-hi 32x136, W-lo
#define ST_BYTES 37888
#define OFF_ALO  10240
#define OFF_WHI  20480
#define OFF_WLO  29184

// ---- fused dual-source pipelined tensor-core GEMM, fp32 via 3-term bf16 ----
// sources: optional fp32 A1 (cvt path, weights W1hi/lo) then optional
// pre-split A2hi/lo (cp.async path, weights W2hi/lo).
// output: fp32 Cf and/or split (Chi, Clo). block tile 128x128, BK=32.
__global__ void __launch_bounds__(256) gemm_tc(
    const float* __restrict__ A1f,
    const bf16* __restrict__ W1hi, const bf16* __restrict__ W1lo,
    const bf16* __restrict__ A2hi, const bf16* __restrict__ A2lo,
    const bf16* __restrict__ W2hi, const bf16* __restrict__ W2lo,
    const float* __restrict__ bias,
    float* __restrict__ Cf, bf16* __restrict__ Chi, bf16* __restrict__ Clo,
    int Nrows, int K, int M, int do_relu)
{
    extern __shared__ __align__(16) char dynsmem[];
    const uint32_t sm0 = smem_u32(dynsmem);

    const int tid  = threadIdx.x;
    const int lane = tid & 31;
    const int warp = tid >> 5;
    const int wm = warp & 1;
    const int wn = warp >> 1;
    const int row0 = blockIdx.y * 128;
    const int col0 = blockIdx.x * 128;

    const bool hasF = (A1f != nullptr);
    const int KT = K / 32;
    const int T  = (hasF ? 2 : 1) * KT;

    float acc[4][4][4];
#pragma unroll
    for (int a = 0; a < 4; a++)
#pragma unroll
        for (int b = 0; b < 4; b++)
#pragma unroll
            for (int c = 0; c < 4; c++) acc[a][b][c] = 0.f;

    float4 vf[4];

    // ---- fill: issue async loads for tile t into stage st ----
    auto fill_async = [&](int t, int st) {
        int s_idx = t / KT;
        int k0 = (t - s_idx * KT) * 32;
        bool isF = hasF && (s_idx == 0);
        const bf16* whi = isF ? W1hi : W2hi;
        const bf16* wlo = isF ? W1lo : W2lo;
        uint32_t sbase = sm0 + st * ST_BYTES;
        // W tile: 32 x 128 bf16, 16B chunks
#pragma unroll
        for (int i = 0; i < 2; i++) {
            int chunk = tid + 256 * i;            // 0..511
            int r = chunk >> 4;
            int cc = (chunk & 15) * 8;            // halves
            uint32_t doff = (uint32_t)(r * 136 + cc) * 2;
            cp16(sbase + OFF_WHI + doff, whi + (size_t)(k0 + r) * M + col0 + cc);
            cp16(sbase + OFF_WLO + doff, wlo + (size_t)(k0 + r) * M + col0 + cc);
        }
        if (isF) {
#pragma unroll
            for (int i = 0; i < 4; i++) {
                int f = tid + 256 * i;
                int r = f >> 3, c4 = (f & 7) * 4;
                int gr = row0 + r;
                vf[i] = (gr < Nrows)
                    ? *reinterpret_cast<const float4*>(A1f + (size_t)gr * K + k0 + c4)
                    : make_float4(0.f, 0.f, 0.f, 0.f);
            }
        } else {
#pragma unroll
            for (int i = 0; i < 4; i++) {
                int chunk = tid + 256 * i;        // 0..1023
                int r = chunk >> 3, c = (chunk & 7) * 4;
                int gr = row0 + r;
                uint32_t dhi = sbase + (uint32_t)(r * 40 + c) * 2;
                if (gr < Nrows) {
                    cp8(dhi,           A2hi + (size_t)gr * K + k0 + c);
                    cp8(dhi + OFF_ALO, A2lo + (size_t)gr * K + k0 + c);
                } else {
                    *reinterpret_cast<uint64_t*>(dynsmem + st * ST_BYTES + (r * 40 + c) * 2) = 0ull;
                    *reinterpret_cast<uint64_t*>(dynsmem + st * ST_BYTES + OFF_ALO + (r * 40 + c) * 2) = 0ull;
                }
            }
        }
    };

    // ---- cvt+STS of prefetched fp32 regs into stage st ----
    auto cvt_sts = [&](int st) {
#pragma unroll
        for (int i = 0; i < 4; i++) {
            int f = tid + 256 * i;
            int r = f >> 3, c4 = (f & 7) * 4;
            float4 v = vf[i];
            bf16 hx = __float2bfloat16(v.x), hy = __float2bfloat16(v.y);
            bf16 hz = __float2bfloat16(v.z), hw = __float2bfloat16(v.w);
            union { bf162 b[2]; uint2 u; } H, L;
            H.b[0] = __halves2bfloat162(hx, hy);
            H.b[1] = __halves2bfloat162(hz, hw);
            L.b[0] = __halves2bfloat162(__float2bfloat16(v.x - __bfloat162float(hx)),
                                        __float2bfloat16(v.y - __bfloat162float(hy)));
            L.b[1] = __halves2bfloat162(__float2bfloat16(v.z - __bfloat162float(hz)),
                                        __float2bfloat16(v.w - __bfloat162float(hw)));
            char* base = dynsmem + st * ST_BYTES + (r * 40 + c4) * 2;
            *reinterpret_cast<uint2*>(base) = H.u;
            *reinterpret_cast<uint2*>(base + OFF_ALO) = L.u;
        }
    };

    auto is_f_tile = [&](int t) { return hasF && (t / KT == 0); };

    // ---- prologue ----
    fill_async(0, 0);
    cp_commit();
    if (is_f_tile(0)) cvt_sts(0);

    for (int t = 0; t < T; t++) {
        int st = t & 1;
        cp_wait0();
        __syncthreads();
        bool more = (t + 1 < T);
        if (more) { fill_async(t + 1, 1 - st); cp_commit(); }

        // ---- compute tile t from stage st ----
        uint32_t aBase = sm0 + st * ST_BYTES;
        uint32_t wBase = aBase + OFF_WHI;
#pragma unroll
        for (int ks = 0; ks < 32; ks += 16) {
            uint32_t ahi[4][4], alo[4][4];
#pragma unroll
            for (int mt = 0; mt < 4; mt++) {
                int r = wm * 64 + mt * 16 + (lane & 15);
                int c = ks + (lane >> 4) * 8;
                uint32_t off = (uint32_t)(r * 40 + c) * 2;
                ldsm_x4(ahi[mt], aBase + off);
                ldsm_x4(alo[mt], aBase + OFF_ALO + off);
            }
#pragma unroll
            for (int nt = 0; nt < 2; nt++) {
                int kr = ks + (lane & 15);
                int c  = wn * 32 + nt * 16 + (lane >> 4) * 8;
                uint32_t off = (uint32_t)(kr * 136 + c) * 2;
                uint32_t bhi[4], blo[4];
                ldsm_x4_t(bhi, wBase + off);
                ldsm_x4_t(blo, wBase + (OFF_WLO - OFF_WHI) + off);
#pragma unroll
                for (int mt = 0; mt < 4; mt++) {
#pragma unroll
                    for (int h = 0; h < 2; h++) {
                        float* cc = acc[mt][nt * 2 + h];
                        mma16816(cc, ahi[mt], &bhi[h * 2]);
                        mma16816(cc, alo[mt], &bhi[h * 2]);
                        mma16816(cc, ahi[mt], &blo[h * 2]);
                    }
                }
            }
        }
        if (more && is_f_tile(t + 1)) cvt_sts(1 - st);
    }

    // ---- epilogue: bias + relu; fp32 and/or split store ----
#pragma unroll
    for (int mt = 0; mt < 4; mt++) {
#pragma unroll
        for (int nt = 0; nt < 4; nt++) {
            int rg = row0 + wm * 64 + mt * 16 + (lane >> 2);
            int cg = col0 + wn * 32 + nt * 8 + (lane & 3) * 2;
            float b0v = 0.f, b1v = 0.f;
            if (bias) { b0v = bias[cg]; b1v = bias[cg + 1]; }
            float o0 = acc[mt][nt][0] + b0v;
            float o1 = acc[mt][nt][1] + b1v;
            float o2 = acc[mt][nt][2] + b0v;
            float o3 = acc[mt][nt][3] + b1v;
            if (do_relu) {
                o0 = fmaxf(o0, 0.f); o1 = fmaxf(o1, 0.f);
                o2 = fmaxf(o2, 0.f); o3 = fmaxf(o3, 0.f);
            }
#pragma unroll
            for (int hrow = 0; hrow < 2; hrow++) {
                int r = rg + hrow * 8;
                if (r >= Nrows) continue;
                float p0 = hrow ? o2 : o0;
                float p1 = hrow ? o3 : o1;
                if (Cf)
                    *reinterpret_cast<float2*>(Cf + (size_t)r * M + cg) = make_float2(p0, p1);
                if (Chi) {
                    bf16 h0b = __float2bfloat16(p0), h1b = __float2bfloat16(p1);
                    *reinterpret_cast<bf162*>(Chi + (size_t)r * M + cg) =
                        __halves2bfloat162(h0b, h1b);
                    *reinterpret_cast<bf162*>(Clo + (size_t)r * M + cg) =
                        __halves2bfloat162(__float2bfloat16(p0 - __bfloat162float(h0b)),
                                           __float2bfloat16(p1 - __bfloat162float(h1b)));
                }
            }
        }
    }
}

// ---------------- launch ----------------
extern "C" void kernel_launch(void* const* d_in, const int* in_sizes, int n_in,
                              void* d_out, int out_size) {
    const float* x   = (const float*)d_in[0];
    const int*   ei  = (const int*)d_in[1];
    const float* Wl0 = (const float*)d_in[2];
    const float* b0  = (const float*)d_in[3];
    const float* Wr0 = (const float*)d_in[4];
    const float* Wl1 = (const float*)d_in[5];
    const float* b1  = (const float*)d_in[6];
    const float* Wr1 = (const float*)d_in[7];
    const float* Wl2 = (const float*)d_in[8];
    const float* b2  = (const float*)d_in[9];
    const float* Wr2 = (const float*)d_in[10];
    float* out = (float*)d_out;

    const int E = in_sizes[1] / 2;

    float *agg0, *agg1, *p2;
    bf16 *xhi, *xlo, *h0hi, *h0lo, *h1hi, *h1lo, *whi, *wlo;
    cudaGetSymbolAddress((void**)&agg0, g_agg0);
    cudaGetSymbolAddress((void**)&agg1, g_agg1);
    cudaGetSymbolAddress((void**)&p2,   g_p2);
    cudaGetSymbolAddress((void**)&xhi,  g_xhi);
    cudaGetSymbolAddress((void**)&xlo,  g_xlo);
    cudaGetSymbolAddress((void**)&h0hi, g_h0hi);
    cudaGetSymbolAddress((void**)&h0lo, g_h0lo);
    cudaGetSymbolAddress((void**)&h1hi, g_h1hi);
    cudaGetSymbolAddress((void**)&h1lo, g_h1lo);
    cudaGetSymbolAddress((void**)&whi,  g_whi);
    cudaGetSymbolAddress((void**)&wlo,  g_wlo);

    static int smem_set = 0;
    if (!smem_set) {
        cudaFuncSetAttribute(gemm_tc, cudaFuncAttributeMaxDynamicSharedMemorySize,
                             2 * ST_BYTES);
        smem_set = 1;
    }

    detect_kernel<<<1, 32>>>(ei);
    zero_all_kernel<<<2048, 256>>>();
    count_kernel<<<(E + 255) / 256, 256>>>(ei, E);
    inv_kernel<<<(N_NODES + 255) / 256, 256>>>();

    // split x and the six weight matrices to bf16 hi/lo
    auto launch_split = [&](const float* s, bf16* h, bf16* l, int n) {
        int n4 = n / 4;
        split4_kernel<<<(n4 + 255) / 256, 256>>>((const float4*)s, (bf162*)h, (bf162*)l, n4);
    };
    launch_split(x,   xhi, xlo, N_NODES * D_IN);
    launch_split(Wl0, whi + OFF_WL0, wlo + OFF_WL0, D_IN * D_H);
    launch_split(Wr0, whi + OFF_WR0, wlo + OFF_WR0, D_IN * D_H);
    launch_split(Wl1, whi + OFF_WL1, wlo + OFF_WL1, D_H * D_H);
    launch_split(Wr1, whi + OFF_WR1, wlo + OFF_WR1, D_H * D_H);
    launch_split(Wl2, whi + OFF_WL2, wlo + OFF_WL2, D_H * D_IN);
    launch_split(Wr2, whi + OFF_WR2, wlo + OFF_WR2, D_H * D_IN);

    const int sblocks = (E + 7) / 8;
    const int gy = (N_NODES + 127) / 128;
    dim3 gH(D_H / 128, gy);
    dim3 gO(D_IN / 128, gy);
    const int smem = 2 * ST_BYTES;

    // layer 0
    scatter_kernel<D_IN><<<sblocks, 256>>>(x, ei, agg0, E);
    gemm_tc<<<gH, 256, smem>>>(agg0, whi + OFF_WL0, wlo + OFF_WL0,
                               xhi, xlo, whi + OFF_WR0, wlo + OFF_WR0,
                               b0, nullptr, h0hi, h0lo, N_NODES, D_IN, D_H, 1);
    // layer 1
    scatter_split_kernel<D_H><<<sblocks, 256>>>(h0hi, h0lo, ei, agg1, E);
    gemm_tc<<<gH, 256, smem>>>(agg1, whi + OFF_WL1, wlo + OFF_WL1,
                               h0hi, h0lo, whi + OFF_WR1, wlo + OFF_WR1,
                               b1, nullptr, h1hi, h1lo, N_NODES, D_H, D_H, 1);
    // layer 2 (project-first)
    gemm_tc<<<gO, 256, smem>>>(nullptr, nullptr, nullptr,
                               h1hi, h1lo, whi + OFF_WL2, wlo + OFF_WL2,
                               nullptr, p2, nullptr, nullptr, N_NODES, D_H, D_IN, 0);
    gemm_tc<<<gO, 256, smem>>>(nullptr, nullptr, nullptr,
                               h1hi, h1lo, whi + OFF_WR2, wlo + OFF_WR2,
                               b2, out, nullptr, nullptr, N_NODES, D_H, D_IN, 0);
    scatter_kernel<D_IN><<<sblocks, 256>>>(p2, ei, out, E);
}

// round 5
// speedup vs baseline: 2.3304x; 1.5166x over previous
#include <cuda_runtime.h>
#include <cuda_bf16.h>
#include <cstdint>

#define N_NODES 50000
#define N_EDGES_MAX 800000
#define D_IN 128
#define D_H 256

typedef __nv_bfloat16 bf16;
typedef __nv_bfloat162 bf162;

// ---------------- scratch (device globals: no allocs allowed) ----------------
__device__ __align__(16) bf16  g_a0hi[(size_t)N_NODES * D_IN];
__device__ __align__(16) bf16  g_a0lo[(size_t)N_NODES * D_IN];
__device__ __align__(16) bf16  g_a1hi[(size_t)N_NODES * D_H];
__device__ __align__(16) bf16  g_a1lo[(size_t)N_NODES * D_H];
__device__ __align__(16) float g_p2  [(size_t)N_NODES * D_IN];
__device__ __align__(16) bf16  g_xhi [(size_t)N_NODES * D_IN];
__device__ __align__(16) bf16  g_xlo [(size_t)N_NODES * D_IN];
__device__ __align__(16) bf16  g_h0hi[(size_t)N_NODES * D_H];
__device__ __align__(16) bf16  g_h0lo[(size_t)N_NODES * D_H];
__device__ __align__(16) bf16  g_h1hi[(size_t)N_NODES * D_H];
__device__ __align__(16) bf16  g_h1lo[(size_t)N_NODES * D_H];
__device__ __align__(16) bf16  g_whi [262144];
__device__ __align__(16) bf16  g_wlo [262144];
__device__ int g_cnt[N_NODES];
__device__ int g_cur[N_NODES];
__device__ int g_rowptr[N_NODES + 1];
__device__ int g_csr[N_EDGES_MAX];
__device__ int g_i64;

// weight offsets inside g_whi/g_wlo (elements)
#define OFF_WL0 0
#define OFF_WR0 32768
#define OFF_WL1 65536
#define OFF_WR1 131072
#define OFF_W2P 196608   // packed [Wl2 | Wr2], 256 x 256

// ---------------- dtype detection (int64 vs silently-downcast int32) --------
__global__ void detect_kernel(const int* __restrict__ ei) {
    if (threadIdx.x == 0 && blockIdx.x == 0) {
        int all0 = 1;
        for (int i = 0; i < 256; i++)
            if (ei[2 * i + 1] != 0) { all0 = 0; break; }
        g_i64 = all0;
    }
}
__device__ __forceinline__ int load_src(const int* ei, int i, int E, int i64) {
    return i64 ? ei[2 * i] : ei[i];
}
__device__ __forceinline__ int load_dst(const int* ei, int i, int E, int i64) {
    return i64 ? ei[2 * (E + i)] : ei[E + i];
}

// ---------------- CSR build ----------------
__global__ void zero_cc_kernel() {
    int i = blockIdx.x * blockDim.x + threadIdx.x;
    if (i < N_NODES) { g_cnt[i] = 0; g_cur[i] = 0; }
}
__global__ void count_kernel(const int* __restrict__ ei, int E) {
    int i = blockIdx.x * blockDim.x + threadIdx.x;
    if (i < E) atomicAdd(&g_cnt[load_dst(ei, i, E, g_i64)], 1);
}
// single-block exclusive scan of g_cnt -> g_rowptr
__global__ void scan_kernel() {
    __shared__ int warpsum[32];
    __shared__ int s_carry;
    const int tid = threadIdx.x;
    const int lane = tid & 31;
    const int wid = tid >> 5;
    if (tid == 0) s_carry = 0;
    __syncthreads();
    for (int base = 0; base < N_NODES; base += 1024) {
        int i = base + tid;
        int v = (i < N_NODES) ? g_cnt[i] : 0;
        int x = v;
#pragma unroll
        for (int d = 1; d < 32; d <<= 1) {
            int y = __shfl_up_sync(0xffffffffu, x, d);
            if (lane >= d) x += y;
        }
        if (lane == 31) warpsum[wid] = x;
        __syncthreads();
        if (wid == 0) {
            int t = warpsum[lane];
#pragma unroll
            for (int d = 1; d < 32; d <<= 1) {
                int y = __shfl_up_sync(0xffffffffu, t, d);
                if (lane >= d) t += y;
            }
            warpsum[lane] = t;
        }
        __syncthreads();
        int excl = (x - v) + (wid > 0 ? warpsum[wid - 1] : 0) + s_carry;
        if (i < N_NODES) g_rowptr[i] = excl;
        __syncthreads();
        if (tid == 0) s_carry += warpsum[31];
        __syncthreads();
    }
    if (threadIdx.x == 0) g_rowptr[N_NODES] = s_carry;
}
__global__ void fill_kernel(const int* __restrict__ ei, int E) {
    int i = blockIdx.x * blockDim.x + threadIdx.x;
    if (i < E) {
        int i64 = g_i64;
        int s = load_src(ei, i, E, i64);
        int d = load_dst(ei, i, E, i64);
        int pos = g_rowptr[d] + atomicAdd(&g_cur[d], 1);
        g_csr[pos] = s;
    }
}

// ---------------- fp32 -> (hi, lo) bf16 pack-split ----------------
// dst element index = r * dstStride + colOff + c  (src is rows x cols row-major)
__global__ void pack_split_kernel(const float4* __restrict__ src,
                                  bf162* __restrict__ hi, bf162* __restrict__ lo,
                                  int n4, int cols4, int dstStride, int colOff) {
    int i = blockIdx.x * blockDim.x + threadIdx.x;
    if (i >= n4) return;
    int r = i / cols4;
    int c = (i - r * cols4) * 4;
    float4 v = src[i];
    bf16 hx = __float2bfloat16(v.x), hy = __float2bfloat16(v.y);
    bf16 hz = __float2bfloat16(v.z), hw = __float2bfloat16(v.w);
    int d2 = (r * dstStride + colOff + c) >> 1;
    hi[d2]     = __halves2bfloat162(hx, hy);
    hi[d2 + 1] = __halves2bfloat162(hz, hw);
    lo[d2]     = __halves2bfloat162(__float2bfloat16(v.x - __bfloat162float(hx)),
                                    __float2bfloat16(v.y - __bfloat162float(hy)));
    lo[d2 + 1] = __halves2bfloat162(__float2bfloat16(v.z - __bfloat162float(hz)),
                                    __float2bfloat16(v.w - __bfloat162float(hw)));
}

// ---------------- CSR gathers (one warp per node, mean folded in) ----------
// D=128 fp32 in -> split bf16 out
__global__ void gather_f2s_128(const float* __restrict__ feat,
                               bf16* __restrict__ ohi, bf16* __restrict__ olo) {
    int node = (int)((blockIdx.x * (unsigned)blockDim.x + threadIdx.x) >> 5);
    if (node >= N_NODES) return;
    int lane = threadIdx.x & 31;
    int beg = g_rowptr[node], end = g_rowptr[node + 1];
    const float4* f4 = reinterpret_cast<const float4*>(feat);
    float4 acc = make_float4(0.f, 0.f, 0.f, 0.f);
    int e = beg;
    for (; e + 4 <= end; e += 4) {
        int s0 = g_csr[e], s1 = g_csr[e + 1], s2 = g_csr[e + 2], s3 = g_csr[e + 3];
        float4 v0 = __ldg(f4 + (size_t)s0 * 32 + lane);
        float4 v1 = __ldg(f4 + (size_t)s1 * 32 + lane);
        float4 v2 = __ldg(f4 + (size_t)s2 * 32 + lane);
        float4 v3 = __ldg(f4 + (size_t)s3 * 32 + lane);
        acc.x += (v0.x + v1.x) + (v2.x + v3.x);
        acc.y += (v0.y + v1.y) + (v2.y + v3.y);
        acc.z += (v0.z + v1.z) + (v2.z + v3.z);
        acc.w += (v0.w + v1.w) + (v2.w + v3.w);
    }
    for (; e < end; e++) {
        float4 v = __ldg(f4 + (size_t)g_csr[e] * 32 + lane);
        acc.x += v.x; acc.y += v.y; acc.z += v.z; acc.w += v.w;
    }
    int c = end - beg;
    float w = 1.0f / (float)(c > 0 ? c : 1);
    acc.x *= w; acc.y *= w; acc.z *= w; acc.w *= w;
    bf16 hx = __float2bfloat16(acc.x), hy = __float2bfloat16(acc.y);
    bf16 hz = __float2bfloat16(acc.z), hw = __float2bfloat16(acc.w);
    union { bf162 b[2]; uint2 u; } H, L;
    H.b[0] = __halves2bfloat162(hx, hy);
    H.b[1] = __halves2bfloat162(hz, hw);
    L.b[0] = __halves2bfloat162(__float2bfloat16(acc.x - __bfloat162float(hx)),
                                __float2bfloat16(acc.y - __bfloat162float(hy)));
    L.b[1] = __halves2bfloat162(__float2bfloat16(acc.z - __bfloat162float(hz)),
                                __float2bfloat16(acc.w - __bfloat162float(hw)));
    reinterpret_cast<uint2*>(ohi)[(size_t)node * 32 + lane] = H.u;
    reinterpret_cast<uint2*>(olo)[(size_t)node * 32 + lane] = L.u;
}

// D=256 split in -> split out
__global__ void gather_s2s_256(const bf16* __restrict__ fhi, const bf16* __restrict__ flo,
                               bf16* __restrict__ ohi, bf16* __restrict__ olo) {
    int node = (int)((blockIdx.x * (unsigned)blockDim.x + threadIdx.x) >> 5);
    if (node >= N_NODES) return;
    int lane = threadIdx.x & 31;
    int beg = g_rowptr[node], end = g_rowptr[node + 1];
    const uint4* h4 = reinterpret_cast<const uint4*>(fhi);
    const uint4* l4 = reinterpret_cast<const uint4*>(flo);
    float acc[8];
#pragma unroll
    for (int k = 0; k < 8; k++) acc[k] = 0.f;

    auto addrow = [&](uint4 H, uint4 L) {
        const uint32_t hs[4] = {H.x, H.y, H.z, H.w};
        const uint32_t ls[4] = {L.x, L.y, L.z, L.w};
#pragma unroll
        for (int k = 0; k < 4; k++) {
            bf162 hb = *reinterpret_cast<const bf162*>(&hs[k]);
            bf162 lb = *reinterpret_cast<const bf162*>(&ls[k]);
            acc[2 * k]     += __bfloat162float(hb.x) + __bfloat162float(lb.x);
            acc[2 * k + 1] += __bfloat162float(hb.y) + __bfloat162float(lb.y);
        }
    };
    int e = beg;
    for (; e + 2 <= end; e += 2) {
        int s0 = g_csr[e], s1 = g_csr[e + 1];
        uint4 H0 = __ldg(h4 + (size_t)s0 * 32 + lane);
        uint4 L0 = __ldg(l4 + (size_t)s0 * 32 + lane);
        uint4 H1 = __ldg(h4 + (size_t)s1 * 32 + lane);
        uint4 L1 = __ldg(l4 + (size_t)s1 * 32 + lane);
        addrow(H0, L0); addrow(H1, L1);
    }
    for (; e < end; e++) {
        int s = g_csr[e];
        addrow(__ldg(h4 + (size_t)s * 32 + lane), __ldg(l4 + (size_t)s * 32 + lane));
    }
    int c = end - beg;
    float w = 1.0f / (float)(c > 0 ? c : 1);
    union { bf162 b[4]; uint4 u; } H, L;
#pragma unroll
    for (int k = 0; k < 4; k++) {
        float v0 = acc[2 * k] * w, v1 = acc[2 * k + 1] * w;
        bf16 h0b = __float2bfloat16(v0), h1b = __float2bfloat16(v1);
        H.b[k] = __halves2bfloat162(h0b, h1b);
        L.b[k] = __halves2bfloat162(__float2bfloat16(v0 - __bfloat162float(h0b)),
                                    __float2bfloat16(v1 - __bfloat162float(h1b)));
    }
    reinterpret_cast<uint4*>(ohi)[(size_t)node * 32 + lane] = H.u;
    reinterpret_cast<uint4*>(olo)[(size_t)node * 32 + lane] = L.u;
}

// D=128 fp32 in -> out[node] += mean (plain load/store; warp owns the row)
__global__ void gather_add_128(const float* __restrict__ feat, float* __restrict__ out) {
    int node = (int)((blockIdx.x * (unsigned)blockDim.x + threadIdx.x) >> 5);
    if (node >= N_NODES) return;
    int lane = threadIdx.x & 31;
    int beg = g_rowptr[node], end = g_rowptr[node + 1];
    const float4* f4 = reinterpret_cast<const float4*>(feat);
    float4 acc = make_float4(0.f, 0.f, 0.f, 0.f);
    int e = beg;
    for (; e + 4 <= end; e += 4) {
        int s0 = g_csr[e], s1 = g_csr[e + 1], s2 = g_csr[e + 2], s3 = g_csr[e + 3];
        float4 v0 = __ldg(f4 + (size_t)s0 * 32 + lane);
        float4 v1 = __ldg(f4 + (size_t)s1 * 32 + lane);
        float4 v2 = __ldg(f4 + (size_t)s2 * 32 + lane);
        float4 v3 = __ldg(f4 + (size_t)s3 * 32 + lane);
        acc.x += (v0.x + v1.x) + (v2.x + v3.x);
        acc.y += (v0.y + v1.y) + (v2.y + v3.y);
        acc.z += (v0.z + v1.z) + (v2.z + v3.z);
        acc.w += (v0.w + v1.w) + (v2.w + v3.w);
    }
    for (; e < end; e++) {
        float4 v = __ldg(f4 + (size_t)g_csr[e] * 32 + lane);
        acc.x += v.x; acc.y += v.y; acc.z += v.z; acc.w += v.w;
    }
    int c = end - beg;
    float w = 1.0f / (float)(c > 0 ? c : 1);
    float4* o4 = reinterpret_cast<float4*>(out) + (size_t)node * 32 + lane;
    float4 o = *o4;
    o.x += acc.x * w; o.y += acc.y * w; o.z += acc.z * w; o.w += acc.w * w;
    *o4 = o;
}

// ---------------- tensor-core GEMM helpers ----------------
__device__ __forceinline__ uint32_t smem_u32(const void* p) {
    return (uint32_t)__cvta_generic_to_shared(p);
}
__device__ __forceinline__ void ldsm_x4(uint32_t* r, uint32_t a) {
    asm volatile("ldmatrix.sync.aligned.m8n8.x4.shared.b16 {%0,%1,%2,%3}, [%4];"
                 : "=r"(r[0]), "=r"(r[1]), "=r"(r[2]), "=r"(r[3]) : "r"(a));
}
__device__ __forceinline__ void ldsm_x4_t(uint32_t* r, uint32_t a) {
    asm volatile("ldmatrix.sync.aligned.m8n8.x4.trans.shared.b16 {%0,%1,%2,%3}, [%4];"
                 : "=r"(r[0]), "=r"(r[1]), "=r"(r[2]), "=r"(r[3]) : "r"(a));
}
__device__ __forceinline__ void mma16816(float* c, const uint32_t* a, const uint32_t* b) {
    asm volatile("mma.sync.aligned.m16n8k16.row.col.f32.bf16.bf16.f32 "
                 "{%0,%1,%2,%3}, {%4,%5,%6,%7}, {%8,%9}, {%0,%1,%2,%3};"
                 : "+f"(c[0]), "+f"(c[1]), "+f"(c[2]), "+f"(c[3])
                 : "r"(a[0]), "r"(a[1]), "r"(a[2]), "r"(a[3]),
                   "r"(b[0]), "r"(b[1]));
}
__device__ __forceinline__ void cp16(uint32_t dst, const void* src) {
    asm volatile("cp.async.ca.shared.global [%0], [%1], 16;" :: "r"(dst), "l"(src));
}
__device__ __forceinline__ void cp8(uint32_t dst, const void* src) {
    asm volatile("cp.async.ca.shared.global [%0], [%1], 8;" :: "r"(dst), "l"(src));
}
__device__ __forceinline__ void cp_commit() { asm volatile("cp.async.commit_group;"); }
__device__ __forceinline__ void cp_wait0()  { asm volatile("cp.async.wait_group 0;" ::: "memory"); }

// smem stage layout (bytes): A-hi 128x40, A-lo, W-hi 32x136, W-lo
#define ST_BYTES 37888
#define OFF_ALO  10240
#define OFF_WHI  20480
#define OFF_WLO  29184

// ---- fused dual-source pipelined tensor-core GEMM, fp32 via 3-term bf16 ----
// all sources pre-split bf16 (pure cp.async fill). block tile 128x128, BK=32.
// output: split (Chi/Clo, stride M, bias+relu) OR routed fp32: blockIdx.x==0
// -> Cf0 (no bias), ==1 -> Cf1 (+bias), both stride 128.
__global__ void __launch_bounds__(256) gemm_tc(
    const bf16* __restrict__ A1hi, const bf16* __restrict__ A1lo,
    const bf16* __restrict__ W1hi, const bf16* __restrict__ W1lo,
    const bf16* __restrict__ A2hi, const bf16* __restrict__ A2lo,
    const bf16* __restrict__ W2hi, const bf16* __restrict__ W2lo,
    const float* __restrict__ bias,
    bf16* __restrict__ Chi, bf16* __restrict__ Clo,
    float* __restrict__ Cf0, float* __restrict__ Cf1,
    int Nrows, int K, int M, int do_relu)
{
    extern __shared__ __align__(16) char dynsmem[];
    const uint32_t sm0 = smem_u32(dynsmem);

    const int tid  = threadIdx.x;
    const int lane = tid & 31;
    const int warp = tid >> 5;
    const int wm = warp & 1;
    const int wn = warp >> 1;
    const int row0 = blockIdx.y * 128;
    const int col0 = blockIdx.x * 128;

    const bool dual = (A2hi != nullptr);
    const int KT = K / 32;
    const int T  = (dual ? 2 : 1) * KT;

    float acc[4][4][4];
#pragma unroll
    for (int a = 0; a < 4; a++)
#pragma unroll
        for (int b = 0; b < 4; b++)
#pragma unroll
            for (int c = 0; c < 4; c++) acc[a][b][c] = 0.f;

    auto fill_async = [&](int t, int st) {
        int s_idx = t / KT;
        int k0 = (t - s_idx * KT) * 32;
        const bf16* ahi = s_idx ? A2hi : A1hi;
        const bf16* alo = s_idx ? A2lo : A1lo;
        const bf16* whi = s_idx ? W2hi : W1hi;
        const bf16* wlo = s_idx ? W2lo : W1lo;
        uint32_t sbase = sm0 + st * ST_BYTES;
#pragma unroll
        for (int i = 0; i < 2; i++) {
            int chunk = tid + 256 * i;            // 0..511
            int r = chunk >> 4;
            int cc = (chunk & 15) * 8;
            uint32_t doff = (uint32_t)(r * 136 + cc) * 2;
            cp16(sbase + OFF_WHI + doff, whi + (size_t)(k0 + r) * M + col0 + cc);
            cp16(sbase + OFF_WLO + doff, wlo + (size_t)(k0 + r) * M + col0 + cc);
        }
#pragma unroll
        for (int i = 0; i < 4; i++) {
            int chunk = tid + 256 * i;            // 0..1023
            int r = chunk >> 3, c = (chunk & 7) * 4;
            int gr = row0 + r;
            uint32_t dhi = sbase + (uint32_t)(r * 40 + c) * 2;
            if (gr < Nrows) {
                cp8(dhi,           ahi + (size_t)gr * K + k0 + c);
                cp8(dhi + OFF_ALO, alo + (size_t)gr * K + k0 + c);
            } else {
                *reinterpret_cast<uint64_t*>(dynsmem + st * ST_BYTES + (r * 40 + c) * 2) = 0ull;
                *reinterpret_cast<uint64_t*>(dynsmem + st * ST_BYTES + OFF_ALO + (r * 40 + c) * 2) = 0ull;
            }
        }
    };

    fill_async(0, 0);
    cp_commit();

    for (int t = 0; t < T; t++) {
        int st = t & 1;
        cp_wait0();
        __syncthreads();
        if (t + 1 < T) { fill_async(t + 1, 1 - st); cp_commit(); }

        uint32_t aBase = sm0 + st * ST_BYTES;
        uint32_t wBase = aBase + OFF_WHI;
#pragma unroll
        for (int ks = 0; ks < 32; ks += 16) {
            uint32_t ahi[4][4], alo[4][4];
#pragma unroll
            for (int mt = 0; mt < 4; mt++) {
                int r = wm * 64 + mt * 16 + (lane & 15);
                int c = ks + (lane >> 4) * 8;
                uint32_t off = (uint32_t)(r * 40 + c) * 2;
                ldsm_x4(ahi[mt], aBase + off);
                ldsm_x4(alo[mt], aBase + OFF_ALO + off);
            }
#pragma unroll
            for (int nt = 0; nt < 2; nt++) {
                int kr = ks + (lane & 15);
                int c  = wn * 32 + nt * 16 + (lane >> 4) * 8;
                uint32_t off = (uint32_t)(kr * 136 + c) * 2;
                uint32_t bhi[4], blo[4];
                ldsm_x4_t(bhi, wBase + off);
                ldsm_x4_t(blo, wBase + (OFF_WLO - OFF_WHI) + off);
#pragma unroll
                for (int mt = 0; mt < 4; mt++) {
#pragma unroll
                    for (int h = 0; h < 2; h++) {
                        float* cc = acc[mt][nt * 2 + h];
                        mma16816(cc, ahi[mt], &bhi[h * 2]);
                        mma16816(cc, alo[mt], &bhi[h * 2]);
                        mma16816(cc, ahi[mt], &blo[h * 2]);
                    }
                }
            }
        }
        __syncthreads();
    }

    // ---- epilogue ----
    const bool splitOut = (Chi != nullptr);
    float* Cf = (blockIdx.x == 0) ? Cf0 : Cf1;
    const bool useBias = bias && (splitOut || blockIdx.x == 1);
#pragma unroll
    for (int mt = 0; mt < 4; mt++) {
#pragma unroll
        for (int nt = 0; nt < 4; nt++) {
            int rg = row0 + wm * 64 + mt * 16 + (lane >> 2);
            int cg = col0 + wn * 32 + nt * 8 + (lane & 3) * 2;
            int cl = cg & 127;                // local col for routed mode
            float b0v = 0.f, b1v = 0.f;
            if (useBias) {
                int bi = splitOut ? cg : cl;
                b0v = bias[bi]; b1v = bias[bi + 1];
            }
            float o0 = acc[mt][nt][0] + b0v;
            float o1 = acc[mt][nt][1] + b1v;
            float o2 = acc[mt][nt][2] + b0v;
            float o3 = acc[mt][nt][3] + b1v;
            if (do_relu) {
                o0 = fmaxf(o0, 0.f); o1 = fmaxf(o1, 0.f);
                o2 = fmaxf(o2, 0.f); o3 = fmaxf(o3, 0.f);
            }
#pragma unroll
            for (int hrow = 0; hrow < 2; hrow++) {
                int r = rg + hrow * 8;
                if (r >= Nrows) continue;
                float p0 = hrow ? o2 : o0;
                float p1 = hrow ? o3 : o1;
                if (splitOut) {
                    bf16 h0b = __float2bfloat16(p0), h1b = __float2bfloat16(p1);
                    *reinterpret_cast<bf162*>(Chi + (size_t)r * M + cg) =
                        __halves2bfloat162(h0b, h1b);
                    *reinterpret_cast<bf162*>(Clo + (size_t)r * M + cg) =
                        __halves2bfloat162(__float2bfloat16(p0 - __bfloat162float(h0b)),
                                           __float2bfloat16(p1 - __bfloat162float(h1b)));
                } else {
                    *reinterpret_cast<float2*>(Cf + (size_t)r * 128 + cl) =
                        make_float2(p0, p1);
                }
            }
        }
    }
}

// ---------------- launch ----------------
extern "C" void kernel_launch(void* const* d_in, const int* in_sizes, int n_in,
                              void* d_out, int out_size) {
    const float* x   = (const float*)d_in[0];
    const int*   ei  = (const int*)d_in[1];
    const float* Wl0 = (const float*)d_in[2];
    const float* b0  = (const float*)d_in[3];
    const float* Wr0 = (const float*)d_in[4];
    const float* Wl1 = (const float*)d_in[5];
    const float* b1  = (const float*)d_in[6];
    const float* Wr1 = (const float*)d_in[7];
    const float* Wl2 = (const float*)d_in[8];
    const float* b2  = (const float*)d_in[9];
    const float* Wr2 = (const float*)d_in[10];
    float* out = (float*)d_out;

    const int E = in_sizes[1] / 2;

    float *p2;
    bf16 *a0hi, *a0lo, *a1hi, *a1lo, *xhi, *xlo, *h0hi, *h0lo, *h1hi, *h1lo, *whi, *wlo;
    cudaGetSymbolAddress((void**)&p2,   g_p2);
    cudaGetSymbolAddress((void**)&a0hi, g_a0hi);
    cudaGetSymbolAddress((void**)&a0lo, g_a0lo);
    cudaGetSymbolAddress((void**)&a1hi, g_a1hi);
    cudaGetSymbolAddress((void**)&a1lo, g_a1lo);
    cudaGetSymbolAddress((void**)&xhi,  g_xhi);
    cudaGetSymbolAddress((void**)&xlo,  g_xlo);
    cudaGetSymbolAddress((void**)&h0hi, g_h0hi);
    cudaGetSymbolAddress((void**)&h0lo, g_h0lo);
    cudaGetSymbolAddress((void**)&h1hi, g_h1hi);
    cudaGetSymbolAddress((void**)&h1lo, g_h1lo);
    cudaGetSymbolAddress((void**)&whi,  g_whi);
    cudaGetSymbolAddress((void**)&wlo,  g_wlo);

    static int smem_set = 0;
    if (!smem_set) {
        cudaFuncSetAttribute(gemm_tc, cudaFuncAttributeMaxDynamicSharedMemorySize,
                             2 * ST_BYTES);
        smem_set = 1;
    }

    // ---- CSR build ----
    detect_kernel<<<1, 32>>>(ei);
    zero_cc_kernel<<<(N_NODES + 1023) / 1024, 1024>>>();
    count_kernel<<<(E + 255) / 256, 256>>>(ei, E);
    scan_kernel<<<1, 1024>>>();
    fill_kernel<<<(E + 255) / 256, 256>>>(ei, E);

    // ---- splits (x, 4 layer-0/1 weights, packed layer-2 weights) ----
    auto split = [&](const float* s, bf16* h, bf16* l, int rows, int cols,
                     int dstStride, int colOff) {
        int n4 = rows * cols / 4;
        pack_split_kernel<<<(n4 + 255) / 256, 256>>>(
            (const float4*)s, (bf162*)h, (bf162*)l, n4, cols / 4, dstStride, colOff);
    };
    split(x,   xhi, xlo, N_NODES, D_IN, D_IN, 0);
    split(Wl0, whi + OFF_WL0, wlo + OFF_WL0, D_IN, D_H, D_H, 0);
    split(Wr0, whi + OFF_WR0, wlo + OFF_WR0, D_IN, D_H, D_H, 0);
    split(Wl1, whi + OFF_WL1, wlo + OFF_WL1, D_H, D_H, D_H, 0);
    split(Wr1, whi + OFF_WR1, wlo + OFF_WR1, D_H, D_H, D_H, 0);
    split(Wl2, whi + OFF_W2P, wlo + OFF_W2P, D_H, D_IN, 256, 0);    // packed cols 0..127
    split(Wr2, whi + OFF_W2P, wlo + OFF_W2P, D_H, D_IN, 256, 128);  // packed cols 128..255

    const int gwarps = (N_NODES * 32 + 255) / 256;
    const int gy = (N_NODES + 127) / 128;
    dim3 gH(D_H / 128, gy);
    const int smem = 2 * ST_BYTES;

    // layer 0
    gather_f2s_128<<<gwarps, 256>>>(x, a0hi, a0lo);
    gemm_tc<<<gH, 256, smem>>>(a0hi, a0lo, whi + OFF_WL0, wlo + OFF_WL0,
                               xhi, xlo, whi + OFF_WR0, wlo + OFF_WR0,
                               b0, h0hi, h0lo, nullptr, nullptr, N_NODES, D_IN, D_H, 1);
    // layer 1
    gather_s2s_256<<<gwarps, 256>>>(h0hi, h0lo, a1hi, a1lo);
    gemm_tc<<<gH, 256, smem>>>(a1hi, a1lo, whi + OFF_WL1, wlo + OFF_WL1,
                               h0hi, h0lo, whi + OFF_WR1, wlo + OFF_WR1,
                               b1, h1hi, h1lo, nullptr, nullptr, N_NODES, D_H, D_H, 1);
    // layer 2: one M=256 GEMM over packed [Wl2|Wr2]; block.x=0 -> p2, 1 -> out(+b2)
    gemm_tc<<<dim3(2, gy), 256, smem>>>(h1hi, h1lo, whi + OFF_W2P, wlo + OFF_W2P,
                                        nullptr, nullptr, nullptr, nullptr,
                                        b2, nullptr, nullptr, p2, out,
                                        N_NODES, D_H, 256, 0);
    gather_add_128<<<gwarps, 256>>>(p2, out);
}

// round 6
// speedup vs baseline: 2.4604x; 1.0558x over previous
#include <cuda_runtime.h>
#include <cuda_bf16.h>
#include <cstdint>

#define N_NODES 50000
#define N_EDGES_MAX 800000
#define D_IN 128
#define D_H 256
#define SCAN_NBLK ((N_NODES + 1023) / 1024)   // 49

typedef __nv_bfloat16 bf16;
typedef __nv_bfloat162 bf162;

// ---------------- scratch (device globals: no allocs allowed) ----------------
__device__ __align__(16) bf16  g_a0hi[(size_t)N_NODES * D_IN];
__device__ __align__(16) bf16  g_a0lo[(size_t)N_NODES * D_IN];
__device__ __align__(16) bf16  g_a1hi[(size_t)N_NODES * D_H];
__device__ __align__(16) bf16  g_a1lo[(size_t)N_NODES * D_H];
__device__ __align__(16) float g_p2  [(size_t)N_NODES * D_IN];
__device__ __align__(16) bf16  g_xhi [(size_t)N_NODES * D_IN];
__device__ __align__(16) bf16  g_xlo [(size_t)N_NODES * D_IN];
__device__ __align__(16) bf16  g_h0hi[(size_t)N_NODES * D_H];
__device__ __align__(16) bf16  g_h0lo[(size_t)N_NODES * D_H];
__device__ __align__(16) bf16  g_h1hi[(size_t)N_NODES * D_H];
__device__ __align__(16) bf16  g_h1lo[(size_t)N_NODES * D_H];
__device__ __align__(16) bf16  g_whi [262144];
__device__ __align__(16) bf16  g_wlo [262144];
__device__ int g_cnt[N_NODES];
__device__ int g_cur[N_NODES];
__device__ int g_rowptr[N_NODES + 1];
__device__ int g_blksum[SCAN_NBLK];
__device__ int g_csr[N_EDGES_MAX];
__device__ int g_i64;

// weight offsets inside g_whi/g_wlo (elements)
#define OFF_WL0 0
#define OFF_WR0 32768
#define OFF_WL1 65536
#define OFF_WR1 131072
#define OFF_W2P 196608   // packed [Wl2 | Wr2], 256 x 256

// ---------------- dtype detection (int64 vs silently-downcast int32) --------
__global__ void detect_kernel(const int* __restrict__ ei) {
    if (threadIdx.x == 0 && blockIdx.x == 0) {
        int all0 = 1;
        for (int i = 0; i < 256; i++)
            if (ei[2 * i + 1] != 0) { all0 = 0; break; }
        g_i64 = all0;
    }
}
__device__ __forceinline__ int load_src(const int* ei, int i, int E, int i64) {
    return i64 ? ei[2 * i] : ei[i];
}
__device__ __forceinline__ int load_dst(const int* ei, int i, int E, int i64) {
    return i64 ? ei[2 * (E + i)] : ei[E + i];
}

// ---------------- CSR build ----------------
__global__ void zero_cc_kernel() {
    int i = blockIdx.x * blockDim.x + threadIdx.x;
    if (i < N_NODES) { g_cnt[i] = 0; g_cur[i] = 0; }
}
__global__ void count_kernel(const int* __restrict__ ei, int E) {
    int i = blockIdx.x * blockDim.x + threadIdx.x;
    if (i < E) atomicAdd(&g_cnt[load_dst(ei, i, E, g_i64)], 1);
}
// phase 1: per-block exclusive scan + block sums
__global__ void scan1_kernel() {
    __shared__ int ws[32];
    const int tid = threadIdx.x;
    const int lane = tid & 31;
    const int wid = tid >> 5;
    int i = blockIdx.x * 1024 + tid;
    int v = (i < N_NODES) ? g_cnt[i] : 0;
    int x = v;
#pragma unroll
    for (int d = 1; d < 32; d <<= 1) {
        int y = __shfl_up_sync(0xffffffffu, x, d);
        if (lane >= d) x += y;
    }
    if (lane == 31) ws[wid] = x;
    __syncthreads();
    if (wid == 0) {
        int t = ws[lane];
#pragma unroll
        for (int d = 1; d < 32; d <<= 1) {
            int y = __shfl_up_sync(0xffffffffu, t, d);
            if (lane >= d) t += y;
        }
        ws[lane] = t;
    }
    __syncthreads();
    int excl = (x - v) + (wid > 0 ? ws[wid - 1] : 0);
    if (i < N_NODES) g_rowptr[i] = excl;
    if (tid == 1023) g_blksum[blockIdx.x] = excl + v;
}
// phase 2: one warp scans the 49 block sums (exclusive, in place)
__global__ void scan2_kernel(int E) {
    int lane = threadIdx.x;
    int v0 = (lane < SCAN_NBLK) ? g_blksum[lane] : 0;
    int v1 = (32 + lane < SCAN_NBLK) ? g_blksum[32 + lane] : 0;
    int x = v0;
#pragma unroll
    for (int d = 1; d < 32; d <<= 1) {
        int y = __shfl_up_sync(0xffffffffu, x, d);
        if (lane >= d) x += y;
    }
    int tot0 = __shfl_sync(0xffffffffu, x, 31);
    int z = v1;
#pragma unroll
    for (int d = 1; d < 32; d <<= 1) {
        int y = __shfl_up_sync(0xffffffffu, z, d);
        if (lane >= d) z += y;
    }
    if (lane < SCAN_NBLK) g_blksum[lane] = x - v0;
    if (32 + lane < SCAN_NBLK) g_blksum[32 + lane] = tot0 + z - v1;
    if (lane == 0) g_rowptr[N_NODES] = E;
}
// phase 3: add block offsets
__global__ void scan3_kernel() {
    int i = blockIdx.x * blockDim.x + threadIdx.x;
    if (i < N_NODES) g_rowptr[i] += g_blksum[i >> 10];
}
__global__ void fill_kernel(const int* __restrict__ ei, int E) {
    int i = blockIdx.x * blockDim.x + threadIdx.x;
    if (i < E) {
        int i64 = g_i64;
        int s = load_src(ei, i, E, i64);
        int d = load_dst(ei, i, E, i64);
        int pos = g_rowptr[d] + atomicAdd(&g_cur[d], 1);
        g_csr[pos] = s;
    }
}

// ---------------- fp32 -> (hi, lo) bf16 pack-split ----------------
__global__ void pack_split_kernel(const float4* __restrict__ src,
                                  bf162* __restrict__ hi, bf162* __restrict__ lo,
                                  int n4, int cols4, int dstStride, int colOff) {
    int i = blockIdx.x * blockDim.x + threadIdx.x;
    if (i >= n4) return;
    int r = i / cols4;
    int c = (i - r * cols4) * 4;
    float4 v = src[i];
    bf16 hx = __float2bfloat16(v.x), hy = __float2bfloat16(v.y);
    bf16 hz = __float2bfloat16(v.z), hw = __float2bfloat16(v.w);
    int d2 = (r * dstStride + colOff + c) >> 1;
    hi[d2]     = __halves2bfloat162(hx, hy);
    hi[d2 + 1] = __halves2bfloat162(hz, hw);
    lo[d2]     = __halves2bfloat162(__float2bfloat16(v.x - __bfloat162float(hx)),
                                    __float2bfloat16(v.y - __bfloat162float(hy)));
    lo[d2 + 1] = __halves2bfloat162(__float2bfloat16(v.z - __bfloat162float(hz)),
                                    __float2bfloat16(v.w - __bfloat162float(hw)));
}

// ---------------- CSR gathers (one warp per node, mean folded in) ----------
__global__ void gather_f2s_128(const float* __restrict__ feat,
                               bf16* __restrict__ ohi, bf16* __restrict__ olo) {
    int node = (int)((blockIdx.x * (unsigned)blockDim.x + threadIdx.x) >> 5);
    if (node >= N_NODES) return;
    int lane = threadIdx.x & 31;
    int beg = g_rowptr[node], end = g_rowptr[node + 1];
    const float4* f4 = reinterpret_cast<const float4*>(feat);
    float4 acc = make_float4(0.f, 0.f, 0.f, 0.f);
    int e = beg;
    for (; e + 4 <= end; e += 4) {
        int s0 = g_csr[e], s1 = g_csr[e + 1], s2 = g_csr[e + 2], s3 = g_csr[e + 3];
        float4 v0 = __ldg(f4 + (size_t)s0 * 32 + lane);
        float4 v1 = __ldg(f4 + (size_t)s1 * 32 + lane);
        float4 v2 = __ldg(f4 + (size_t)s2 * 32 + lane);
        float4 v3 = __ldg(f4 + (size_t)s3 * 32 + lane);
        acc.x += (v0.x + v1.x) + (v2.x + v3.x);
        acc.y += (v0.y + v1.y) + (v2.y + v3.y);
        acc.z += (v0.z + v1.z) + (v2.z + v3.z);
        acc.w += (v0.w + v1.w) + (v2.w + v3.w);
    }
    for (; e < end; e++) {
        float4 v = __ldg(f4 + (size_t)g_csr[e] * 32 + lane);
        acc.x += v.x; acc.y += v.y; acc.z += v.z; acc.w += v.w;
    }
    int c = end - beg;
    float w = 1.0f / (float)(c > 0 ? c : 1);
    acc.x *= w; acc.y *= w; acc.z *= w; acc.w *= w;
    bf16 hx = __float2bfloat16(acc.x), hy = __float2bfloat16(acc.y);
    bf16 hz = __float2bfloat16(acc.z), hw = __float2bfloat16(acc.w);
    union { bf162 b[2]; uint2 u; } H, L;
    H.b[0] = __halves2bfloat162(hx, hy);
    H.b[1] = __halves2bfloat162(hz, hw);
    L.b[0] = __halves2bfloat162(__float2bfloat16(acc.x - __bfloat162float(hx)),
                                __float2bfloat16(acc.y - __bfloat162float(hy)));
    L.b[1] = __halves2bfloat162(__float2bfloat16(acc.z - __bfloat162float(hz)),
                                __float2bfloat16(acc.w - __bfloat162float(hw)));
    reinterpret_cast<uint2*>(ohi)[(size_t)node * 32 + lane] = H.u;
    reinterpret_cast<uint2*>(olo)[(size_t)node * 32 + lane] = L.u;
}

// D=256 split in -> split out, 4-edge unroll for MLP
__global__ void gather_s2s_256(const bf16* __restrict__ fhi, const bf16* __restrict__ flo,
                               bf16* __restrict__ ohi, bf16* __restrict__ olo) {
    int node = (int)((blockIdx.x * (unsigned)blockDim.x + threadIdx.x) >> 5);
    if (node >= N_NODES) return;
    int lane = threadIdx.x & 31;
    int beg = g_rowptr[node], end = g_rowptr[node + 1];
    const uint4* h4 = reinterpret_cast<const uint4*>(fhi);
    const uint4* l4 = reinterpret_cast<const uint4*>(flo);
    float acc[8];
#pragma unroll
    for (int k = 0; k < 8; k++) acc[k] = 0.f;

    auto addrow = [&](uint4 H, uint4 L) {
        const uint32_t hs[4] = {H.x, H.y, H.z, H.w};
        const uint32_t ls[4] = {L.x, L.y, L.z, L.w};
#pragma unroll
        for (int k = 0; k < 4; k++) {
            bf162 hb = *reinterpret_cast<const bf162*>(&hs[k]);
            bf162 lb = *reinterpret_cast<const bf162*>(&ls[k]);
            acc[2 * k]     += __bfloat162float(hb.x) + __bfloat162float(lb.x);
            acc[2 * k + 1] += __bfloat162float(hb.y) + __bfloat162float(lb.y);
        }
    };
    int e = beg;
    for (; e + 4 <= end; e += 4) {
        int s0 = g_csr[e], s1 = g_csr[e + 1], s2 = g_csr[e + 2], s3 = g_csr[e + 3];
        uint4 H0 = __ldg(h4 + (size_t)s0 * 32 + lane);
        uint4 L0 = __ldg(l4 + (size_t)s0 * 32 + lane);
        uint4 H1 = __ldg(h4 + (size_t)s1 * 32 + lane);
        uint4 L1 = __ldg(l4 + (size_t)s1 * 32 + lane);
        uint4 H2 = __ldg(h4 + (size_t)s2 * 32 + lane);
        uint4 L2 = __ldg(l4 + (size_t)s2 * 32 + lane);
        uint4 H3 = __ldg(h4 + (size_t)s3 * 32 + lane);
        uint4 L3 = __ldg(l4 + (size_t)s3 * 32 + lane);
        addrow(H0, L0); addrow(H1, L1); addrow(H2, L2); addrow(H3, L3);
    }
    for (; e < end; e++) {
        int s = g_csr[e];
        addrow(__ldg(h4 + (size_t)s * 32 + lane), __ldg(l4 + (size_t)s * 32 + lane));
    }
    int c = end - beg;
    float w = 1.0f / (float)(c > 0 ? c : 1);
    union { bf162 b[4]; uint4 u; } H, L;
#pragma unroll
    for (int k = 0; k < 4; k++) {
        float v0 = acc[2 * k] * w, v1 = acc[2 * k + 1] * w;
        bf16 h0b = __float2bfloat16(v0), h1b = __float2bfloat16(v1);
        H.b[k] = __halves2bfloat162(h0b, h1b);
        L.b[k] = __halves2bfloat162(__float2bfloat16(v0 - __bfloat162float(h0b)),
                                    __float2bfloat16(v1 - __bfloat162float(h1b)));
    }
    reinterpret_cast<uint4*>(ohi)[(size_t)node * 32 + lane] = H.u;
    reinterpret_cast<uint4*>(olo)[(size_t)node * 32 + lane] = L.u;
}

// D=128 fp32 in -> out[node] += mean
__global__ void gather_add_128(const float* __restrict__ feat, float* __restrict__ out) {
    int node = (int)((blockIdx.x * (unsigned)blockDim.x + threadIdx.x) >> 5);
    if (node >= N_NODES) return;
    int lane = threadIdx.x & 31;
    int beg = g_rowptr[node], end = g_rowptr[node + 1];
    const float4* f4 = reinterpret_cast<const float4*>(feat);
    float4 acc = make_float4(0.f, 0.f, 0.f, 0.f);
    int e = beg;
    for (; e + 4 <= end; e += 4) {
        int s0 = g_csr[e], s1 = g_csr[e + 1], s2 = g_csr[e + 2], s3 = g_csr[e + 3];
        float4 v0 = __ldg(f4 + (size_t)s0 * 32 + lane);
        float4 v1 = __ldg(f4 + (size_t)s1 * 32 + lane);
        float4 v2 = __ldg(f4 + (size_t)s2 * 32 + lane);
        float4 v3 = __ldg(f4 + (size_t)s3 * 32 + lane);
        acc.x += (v0.x + v1.x) + (v2.x + v3.x);
        acc.y += (v0.y + v1.y) + (v2.y + v3.y);
        acc.z += (v0.z + v1.z) + (v2.z + v3.z);
        acc.w += (v0.w + v1.w) + (v2.w + v3.w);
    }
    for (; e < end; e++) {
        float4 v = __ldg(f4 + (size_t)g_csr[e] * 32 + lane);
        acc.x += v.x; acc.y += v.y; acc.z += v.z; acc.w += v.w;
    }
    int c = end - beg;
    float w = 1.0f / (float)(c > 0 ? c : 1);
    float4* o4 = reinterpret_cast<float4*>(out) + (size_t)node * 32 + lane;
    float4 o = *o4;
    o.x += acc.x * w; o.y += acc.y * w; o.z += acc.z * w; o.w += acc.w * w;
    *o4 = o;
}

// ---------------- tensor-core GEMM helpers ----------------
__device__ __forceinline__ uint32_t smem_u32(const void* p) {
    return (uint32_t)__cvta_generic_to_shared(p);
}
__device__ __forceinline__ void ldsm_x4(uint32_t* r, uint32_t a) {
    asm volatile("ldmatrix.sync.aligned.m8n8.x4.shared.b16 {%0,%1,%2,%3}, [%4];"
                 : "=r"(r[0]), "=r"(r[1]), "=r"(r[2]), "=r"(r[3]) : "r"(a));
}
__device__ __forceinline__ void ldsm_x4_t(uint32_t* r, uint32_t a) {
    asm volatile("ldmatrix.sync.aligned.m8n8.x4.trans.shared.b16 {%0,%1,%2,%3}, [%4];"
                 : "=r"(r[0]), "=r"(r[1]), "=r"(r[2]), "=r"(r[3]) : "r"(a));
}
__device__ __forceinline__ void mma16816(float* c, const uint32_t* a, const uint32_t* b) {
    asm volatile("mma.sync.aligned.m16n8k16.row.col.f32.bf16.bf16.f32 "
                 "{%0,%1,%2,%3}, {%4,%5,%6,%7}, {%8,%9}, {%0,%1,%2,%3};"
                 : "+f"(c[0]), "+f"(c[1]), "+f"(c[2]), "+f"(c[3])
                 : "r"(a[0]), "r"(a[1]), "r"(a[2]), "r"(a[3]),
                   "r"(b[0]), "r"(b[1]));
}
__device__ __forceinline__ void cp16(uint32_t dst, const void* src) {
    asm volatile("cp.async.ca.shared.global [%0], [%1], 16;" :: "r"(dst), "l"(src));
}
__device__ __forceinline__ void cp8(uint32_t dst, const void* src) {
    asm volatile("cp.async.ca.shared.global [%0], [%1], 8;" :: "r"(dst), "l"(src));
}
__device__ __forceinline__ void cp_commit() { asm volatile("cp.async.commit_group;"); }
__device__ __forceinline__ void cp_wait0()  { asm volatile("cp.async.wait_group 0;" ::: "memory"); }

// smem stage layout (bytes): A-hi 128x40, A-lo, W-hi 32x136, W-lo
#define ST_BYTES 37888
#define OFF_ALO  10240
#define OFF_WHI  20480
#define OFF_WLO  29184

// ---- fused dual-source pipelined tensor-core GEMM, fp32 via 3-term bf16 ----
__global__ void __launch_bounds__(256, 2) gemm_tc(
    const bf16* __restrict__ A1hi, const bf16* __restrict__ A1lo,
    const bf16* __restrict__ W1hi, const bf16* __restrict__ W1lo,
    const bf16* __restrict__ A2hi, const bf16* __restrict__ A2lo,
    const bf16* __restrict__ W2hi, const bf16* __restrict__ W2lo,
    const float* __restrict__ bias,
    bf16* __restrict__ Chi, bf16* __restrict__ Clo,
    float* __restrict__ Cf0, float* __restrict__ Cf1,
    int Nrows, int K, int M, int do_relu)
{
    extern __shared__ __align__(16) char dynsmem[];
    const uint32_t sm0 = smem_u32(dynsmem);

    const int tid  = threadIdx.x;
    const int lane = tid & 31;
    const int warp = tid >> 5;
    const int wm = warp & 1;
    const int wn = warp >> 1;
    const int row0 = blockIdx.y * 128;
    const int col0 = blockIdx.x * 128;

    const bool dual = (A2hi != nullptr);
    const int KT = K / 32;
    const int T  = (dual ? 2 : 1) * KT;

    float acc[4][4][4];
#pragma unroll
    for (int a = 0; a < 4; a++)
#pragma unroll
        for (int b = 0; b < 4; b++)
#pragma unroll
            for (int c = 0; c < 4; c++) acc[a][b][c] = 0.f;

    auto fill_async = [&](int t, int st) {
        int s_idx = t / KT;
        int k0 = (t - s_idx * KT) * 32;
        const bf16* ahi = s_idx ? A2hi : A1hi;
        const bf16* alo = s_idx ? A2lo : A1lo;
        const bf16* whi = s_idx ? W2hi : W1hi;
        const bf16* wlo = s_idx ? W2lo : W1lo;
        uint32_t sbase = sm0 + st * ST_BYTES;
#pragma unroll
        for (int i = 0; i < 2; i++) {
            int chunk = tid + 256 * i;
            int r = chunk >> 4;
            int cc = (chunk & 15) * 8;
            uint32_t doff = (uint32_t)(r * 136 + cc) * 2;
            cp16(sbase + OFF_WHI + doff, whi + (size_t)(k0 + r) * M + col0 + cc);
            cp16(sbase + OFF_WLO + doff, wlo + (size_t)(k0 + r) * M + col0 + cc);
        }
#pragma unroll
        for (int i = 0; i < 4; i++) {
            int chunk = tid + 256 * i;
            int r = chunk >> 3, c = (chunk & 7) * 4;
            int gr = row0 + r;
            uint32_t dhi = sbase + (uint32_t)(r * 40 + c) * 2;
            if (gr < Nrows) {
                cp8(dhi,           ahi + (size_t)gr * K + k0 + c);
                cp8(dhi + OFF_ALO, alo + (size_t)gr * K + k0 + c);
            } else {
                *reinterpret_cast<uint64_t*>(dynsmem + st * ST_BYTES + (r * 40 + c) * 2) = 0ull;
                *reinterpret_cast<uint64_t*>(dynsmem + st * ST_BYTES + OFF_ALO + (r * 40 + c) * 2) = 0ull;
            }
        }
    };

    fill_async(0, 0);
    cp_commit();

    for (int t = 0; t < T; t++) {
        int st = t & 1;
        cp_wait0();
        __syncthreads();
        if (t + 1 < T) { fill_async(t + 1, 1 - st); cp_commit(); }

        uint32_t aBase = sm0 + st * ST_BYTES;
        uint32_t wBase = aBase + OFF_WHI;
#pragma unroll
        for (int ks = 0; ks < 32; ks += 16) {
            uint32_t ahi[4][4], alo[4][4];
#pragma unroll
            for (int mt = 0; mt < 4; mt++) {
                int r = wm * 64 + mt * 16 + (lane & 15);
                int c = ks + (lane >> 4) * 8;
                uint32_t off = (uint32_t)(r * 40 + c) * 2;
                ldsm_x4(ahi[mt], aBase + off);
                ldsm_x4(alo[mt], aBase + OFF_ALO + off);
            }
#pragma unroll
            for (int nt = 0; nt < 2; nt++) {
                int kr = ks + (lane & 15);
                int c  = wn * 32 + nt * 16 + (lane >> 4) * 8;
                uint32_t off = (uint32_t)(kr * 136 + c) * 2;
                uint32_t bhi[4], blo[4];
                ldsm_x4_t(bhi, wBase + off);
                ldsm_x4_t(blo, wBase + (OFF_WLO - OFF_WHI) + off);
#pragma unroll
                for (int mt = 0; mt < 4; mt++) {
#pragma unroll
                    for (int h = 0; h < 2; h++) {
                        float* cc = acc[mt][nt * 2 + h];
                        mma16816(cc, ahi[mt], &bhi[h * 2]);
                        mma16816(cc, alo[mt], &bhi[h * 2]);
                        mma16816(cc, ahi[mt], &blo[h * 2]);
                    }
                }
            }
        }
        __syncthreads();
    }

    // ---- epilogue ----
    const bool splitOut = (Chi != nullptr);
    float* Cf = (blockIdx.x == 0) ? Cf0 : Cf1;
    const bool useBias = bias && (splitOut || blockIdx.x == 1);
#pragma unroll
    for (int mt = 0; mt < 4; mt++) {
#pragma unroll
        for (int nt = 0; nt < 4; nt++) {
            int rg = row0 + wm * 64 + mt * 16 + (lane >> 2);
            int cg = col0 + wn * 32 + nt * 8 + (lane & 3) * 2;
            int cl = cg & 127;
            float b0v = 0.f, b1v = 0.f;
            if (useBias) {
                int bi = splitOut ? cg : cl;
                b0v = bias[bi]; b1v = bias[bi + 1];
            }
            float o0 = acc[mt][nt][0] + b0v;
            float o1 = acc[mt][nt][1] + b1v;
            float o2 = acc[mt][nt][2] + b0v;
            float o3 = acc[mt][nt][3] + b1v;
            if (do_relu) {
                o0 = fmaxf(o0, 0.f); o1 = fmaxf(o1, 0.f);
                o2 = fmaxf(o2, 0.f); o3 = fmaxf(o3, 0.f);
            }
#pragma unroll
            for (int hrow = 0; hrow < 2; hrow++) {
                int r = rg + hrow * 8;
                if (r >= Nrows) continue;
                float p0 = hrow ? o2 : o0;
                float p1 = hrow ? o3 : o1;
                if (splitOut) {
                    bf16 h0b = __float2bfloat16(p0), h1b = __float2bfloat16(p1);
                    *reinterpret_cast<bf162*>(Chi + (size_t)r * M + cg) =
                        __halves2bfloat162(h0b, h1b);
                    *reinterpret_cast<bf162*>(Clo + (size_t)r * M + cg) =
                        __halves2bfloat162(__float2bfloat16(p0 - __bfloat162float(h0b)),
                                           __float2bfloat16(p1 - __bfloat162float(h1b)));
                } else {
                    *reinterpret_cast<float2*>(Cf + (size_t)r * 128 + cl) =
                        make_float2(p0, p1);
                }
            }
        }
    }
}

// ---------------- launch ----------------
extern "C" void kernel_launch(void* const* d_in, const int* in_sizes, int n_in,
                              void* d_out, int out_size) {
    const float* x   = (const float*)d_in[0];
    const int*   ei  = (const int*)d_in[1];
    const float* Wl0 = (const float*)d_in[2];
    const float* b0  = (const float*)d_in[3];
    const float* Wr0 = (const float*)d_in[4];
    const float* Wl1 = (const float*)d_in[5];
    const float* b1  = (const float*)d_in[6];
    const float* Wr1 = (const float*)d_in[7];
    const float* Wl2 = (const float*)d_in[8];
    const float* b2  = (const float*)d_in[9];
    const float* Wr2 = (const float*)d_in[10];
    float* out = (float*)d_out;

    const int E = in_sizes[1] / 2;

    float *p2;
    bf16 *a0hi, *a0lo, *a1hi, *a1lo, *xhi, *xlo, *h0hi, *h0lo, *h1hi, *h1lo, *whi, *wlo;
    cudaGetSymbolAddress((void**)&p2,   g_p2);
    cudaGetSymbolAddress((void**)&a0hi, g_a0hi);
    cudaGetSymbolAddress((void**)&a0lo, g_a0lo);
    cudaGetSymbolAddress((void**)&a1hi, g_a1hi);
    cudaGetSymbolAddress((void**)&a1lo, g_a1lo);
    cudaGetSymbolAddress((void**)&xhi,  g_xhi);
    cudaGetSymbolAddress((void**)&xlo,  g_xlo);
    cudaGetSymbolAddress((void**)&h0hi, g_h0hi);
    cudaGetSymbolAddress((void**)&h0lo, g_h0lo);
    cudaGetSymbolAddress((void**)&h1hi, g_h1hi);
    cudaGetSymbolAddress((void**)&h1lo, g_h1lo);
    cudaGetSymbolAddress((void**)&whi,  g_whi);
    cudaGetSymbolAddress((void**)&wlo,  g_wlo);

    static int smem_set = 0;
    if (!smem_set) {
        cudaFuncSetAttribute(gemm_tc, cudaFuncAttributeMaxDynamicSharedMemorySize,
                             2 * ST_BYTES);
        smem_set = 1;
    }

    // ---- CSR build ----
    detect_kernel<<<1, 32>>>(ei);
    zero_cc_kernel<<<(N_NODES + 1023) / 1024, 1024>>>();
    count_kernel<<<(E + 255) / 256, 256>>>(ei, E);
    scan1_kernel<<<SCAN_NBLK, 1024>>>();
    scan2_kernel<<<1, 32>>>(E);
    scan3_kernel<<<(N_NODES + 1023) / 1024, 1024>>>();
    fill_kernel<<<(E + 255) / 256, 256>>>(ei, E);

    // ---- splits ----
    auto split = [&](const float* s, bf16* h, bf16* l, int rows, int cols,
                     int dstStride, int colOff) {
        int n4 = rows * cols / 4;
        pack_split_kernel<<<(n4 + 255) / 256, 256>>>(
            (const float4*)s, (bf162*)h, (bf162*)l, n4, cols / 4, dstStride, colOff);
    };
    split(x,   xhi, xlo, N_NODES, D_IN, D_IN, 0);
    split(Wl0, whi + OFF_WL0, wlo + OFF_WL0, D_IN, D_H, D_H, 0);
    split(Wr0, whi + OFF_WR0, wlo + OFF_WR0, D_IN, D_H, D_H, 0);
    split(Wl1, whi + OFF_WL1, wlo + OFF_WL1, D_H, D_H, D_H, 0);
    split(Wr1, whi + OFF_WR1, wlo + OFF_WR1, D_H, D_H, D_H, 0);
    split(Wl2, whi + OFF_W2P, wlo + OFF_W2P, D_H, D_IN, 256, 0);
    split(Wr2, whi + OFF_W2P, wlo + OFF_W2P, D_H, D_IN, 256, 128);

    const int gwarps = (N_NODES * 32 + 255) / 256;
    const int gy = (N_NODES + 127) / 128;
    dim3 gH(D_H / 128, gy);
    const int smem = 2 * ST_BYTES;

    // layer 0
    gather_f2s_128<<<gwarps, 256>>>(x, a0hi, a0lo);
    gemm_tc<<<gH, 256, smem>>>(a0hi, a0lo, whi + OFF_WL0, wlo + OFF_WL0,
                               xhi, xlo, whi + OFF_WR0, wlo + OFF_WR0,
                               b0, h0hi, h0lo, nullptr, nullptr, N_NODES, D_IN, D_H, 1);
    // layer 1
    gather_s2s_256<<<gwarps, 256>>>(h0hi, h0lo, a1hi, a1lo);
    gemm_tc<<<gH, 256, smem>>>(a1hi, a1lo, whi + OFF_WL1, wlo + OFF_WL1,
                               h0hi, h0lo, whi + OFF_WR1, wlo + OFF_WR1,
                               b1, h1hi, h1lo, nullptr, nullptr, N_NODES, D_H, D_H, 1);
    // layer 2: one M=256 GEMM over packed [Wl2|Wr2]; block.x=0 -> p2, 1 -> out(+b2)
    gemm_tc<<<dim3(2, gy), 256, smem>>>(h1hi, h1lo, whi + OFF_W2P, wlo + OFF_W2P,
                                        nullptr, nullptr, nullptr, nullptr,
                                        b2, nullptr, nullptr, p2, out,
                                        N_NODES, D_H, 256, 0);
    gather_add_128<<<gwarps, 256>>>(p2, out);
}

// round 9
// speedup vs baseline: 2.6483x; 1.0764x over previous
#include <cuda_runtime.h>
#include <cuda_bf16.h>
#include <cstdint>

#define N_NODES 50000
#define N_PAD   50048
#define N_EDGES_MAX 800000
#define D_IN 128
#define D_H 256
#define SCAN_NBLK ((N_NODES + 1023) / 1024)   // 49

typedef __nv_bfloat16 bf16;
typedef __nv_bfloat162 bf162;

// ---------------- scratch (device globals: no allocs allowed) ----------------
// Combined split layout: each row = [hi(0..K) | lo(K..2K)]. Padded rows stay 0.
__device__ __align__(16) bf16  g_x  [(size_t)N_PAD * 256];   // x split, K=128
__device__ __align__(16) bf16  g_a0 [(size_t)N_PAD * 256];   // agg(x), K=128
__device__ __align__(16) bf16  g_h0 [(size_t)N_PAD * 512];   // h0, K=256
__device__ __align__(16) bf16  g_a1 [(size_t)N_PAD * 512];   // agg(h0), K=256
__device__ __align__(16) bf16  g_h1 [(size_t)N_PAD * 512];   // h1, K=256
__device__ __align__(16) float g_p2 [(size_t)N_PAD * D_IN];
__device__ __align__(16) bf16  g_whi[262144];
__device__ __align__(16) bf16  g_wlo[262144];
__device__ int g_cnt[N_NODES];
__device__ int g_cur[N_NODES];
__device__ int g_rowptr[N_NODES + 1];
__device__ int g_blksum[SCAN_NBLK];
__device__ int g_csr[N_EDGES_MAX];
__device__ int g_i64;

// weight offsets inside g_whi/g_wlo (elements); W stored [K x M] row-major
#define OFF_WL0 0
#define OFF_WR0 32768
#define OFF_WL1 65536
#define OFF_WR1 131072
#define OFF_W2P 196608   // packed [Wl2 | Wr2], 256 x 256

// ---------------- dtype detection (int64 vs silently-downcast int32) --------
__global__ void detect_kernel(const int* __restrict__ ei) {
    if (threadIdx.x == 0 && blockIdx.x == 0) {
        int all0 = 1;
        for (int i = 0; i < 256; i++)
            if (ei[2 * i + 1] != 0) { all0 = 0; break; }
        g_i64 = all0;
    }
}
__device__ __forceinline__ int load_src(const int* ei, int i, int E, int i64) {
    return i64 ? ei[2 * i] : ei[i];
}
__device__ __forceinline__ int load_dst(const int* ei, int i, int E, int i64) {
    return i64 ? ei[2 * (E + i)] : ei[E + i];
}

// ---------------- CSR build ----------------
__global__ void zero_cc_kernel() {
    int i = blockIdx.x * blockDim.x + threadIdx.x;
    if (i < N_NODES) { g_cnt[i] = 0; g_cur[i] = 0; }
}
__global__ void count_kernel(const int* __restrict__ ei, int E) {
    int i = blockIdx.x * blockDim.x + threadIdx.x;
    if (i < E) atomicAdd(&g_cnt[load_dst(ei, i, E, g_i64)], 1);
}
__global__ void scan1_kernel() {
    __shared__ int ws[32];
    const int tid = threadIdx.x;
    const int lane = tid & 31;
    const int wid = tid >> 5;
    int i = blockIdx.x * 1024 + tid;
    int v = (i < N_NODES) ? g_cnt[i] : 0;
    int x = v;
#pragma unroll
    for (int d = 1; d < 32; d <<= 1) {
        int y = __shfl_up_sync(0xffffffffu, x, d);
        if (lane >= d) x += y;
    }
    if (lane == 31) ws[wid] = x;
    __syncthreads();
    if (wid == 0) {
        int t = ws[lane];
#pragma unroll
        for (int d = 1; d < 32; d <<= 1) {
            int y = __shfl_up_sync(0xffffffffu, t, d);
            if (lane >= d) t += y;
        }
        ws[lane] = t;
    }
    __syncthreads();
    int excl = (x - v) + (wid > 0 ? ws[wid - 1] : 0);
    if (i < N_NODES) g_rowptr[i] = excl;
    if (tid == 1023) g_blksum[blockIdx.x] = excl + v;
}
__global__ void scan2_kernel(int E) {
    int lane = threadIdx.x;
    int v0 = (lane < SCAN_NBLK) ? g_blksum[lane] : 0;
    int v1 = (32 + lane < SCAN_NBLK) ? g_blksum[32 + lane] : 0;
    int x = v0;
#pragma unroll
    for (int d = 1; d < 32; d <<= 1) {
        int y = __shfl_up_sync(0xffffffffu, x, d);
        if (lane >= d) x += y;
    }
    int tot0 = __shfl_sync(0xffffffffu, x, 31);
    int z = v1;
#pragma unroll
    for (int d = 1; d < 32; d <<= 1) {
        int y = __shfl_up_sync(0xffffffffu, z, d);
        if (lane >= d) z += y;
    }
    if (lane < SCAN_NBLK) g_blksum[lane] = x - v0;
    if (32 + lane < SCAN_NBLK) g_blksum[32 + lane] = tot0 + z - v1;
    if (lane == 0) g_rowptr[N_NODES] = E;
}
__global__ void scan3_kernel() {
    int i = blockIdx.x * blockDim.x + threadIdx.x;
    if (i < N_NODES) g_rowptr[i] += g_blksum[i >> 10];
}
__global__ void fill_kernel(const int* __restrict__ ei, int E) {
    int i = blockIdx.x * blockDim.x + threadIdx.x;
    if (i < E) {
        int i64 = g_i64;
        int s = load_src(ei, i, E, i64);
        int d = load_dst(ei, i, E, i64);
        int pos = g_rowptr[d] + atomicAdd(&g_cur[d], 1);
        g_csr[pos] = s;
    }
}

// ---------------- splits ----------------
// x: fp32 [N x 128] -> combined split rows [hi(128)|lo(128)]
__global__ void pack_split_x(const float4* __restrict__ src, bf162* __restrict__ dst, int n4) {
    int i = blockIdx.x * blockDim.x + threadIdx.x;
    if (i >= n4) return;
    int r = i >> 5;                 // 32 float4 per row
    int c = (i & 31) * 4;           // col
    float4 v = src[i];
    bf16 hx = __float2bfloat16(v.x), hy = __float2bfloat16(v.y);
    bf16 hz = __float2bfloat16(v.z), hw = __float2bfloat16(v.w);
    int h2 = (r * 256 + c) >> 1;
    dst[h2]     = __halves2bfloat162(hx, hy);
    dst[h2 + 1] = __halves2bfloat162(hz, hw);
    int l2 = h2 + 64;               // +128 elements
    dst[l2]     = __halves2bfloat162(__float2bfloat16(v.x - __bfloat162float(hx)),
                                     __float2bfloat16(v.y - __bfloat162float(hy)));
    dst[l2 + 1] = __halves2bfloat162(__float2bfloat16(v.z - __bfloat162float(hz)),
                                     __float2bfloat16(v.w - __bfloat162float(hw)));
}

// weights: fp32 [rows x cols] -> hi/lo arrays at dst element r*dstStride+colOff+c
__global__ void pack_split_w(const float4* __restrict__ src,
                             bf162* __restrict__ hi, bf162* __restrict__ lo,
                             int n4, int cols4, int dstStride, int colOff) {
    int i = blockIdx.x * blockDim.x + threadIdx.x;
    if (i >= n4) return;
    int r = i / cols4;
    int c = (i - r * cols4) * 4;
    float4 v = src[i];
    bf16 hx = __float2bfloat16(v.x), hy = __float2bfloat16(v.y);
    bf16 hz = __float2bfloat16(v.z), hw = __float2bfloat16(v.w);
    int d2 = (r * dstStride + colOff + c) >> 1;
    hi[d2]     = __halves2bfloat162(hx, hy);
    hi[d2 + 1] = __halves2bfloat162(hz, hw);
    lo[d2]     = __halves2bfloat162(__float2bfloat16(v.x - __bfloat162float(hx)),
                                    __float2bfloat16(v.y - __bfloat162float(hy)));
    lo[d2 + 1] = __halves2bfloat162(__float2bfloat16(v.z - __bfloat162float(hz)),
                                    __float2bfloat16(v.w - __bfloat162float(hw)));
}

// ---------------- CSR gathers (one warp per node, mean folded in) ----------
// D=128 fp32 in -> combined split out (row [hi128|lo128])
__global__ void gather_f2s_128(const float* __restrict__ feat, bf16* __restrict__ o) {
    int node = (int)((blockIdx.x * (unsigned)blockDim.x + threadIdx.x) >> 5);
    if (node >= N_NODES) return;
    int lane = threadIdx.x & 31;
    int beg = g_rowptr[node], end = g_rowptr[node + 1];
    const float4* f4 = reinterpret_cast<const float4*>(feat);
    float4 acc = make_float4(0.f, 0.f, 0.f, 0.f);
    int e = beg;
    for (; e + 4 <= end; e += 4) {
        int s0 = g_csr[e], s1 = g_csr[e + 1], s2 = g_csr[e + 2], s3 = g_csr[e + 3];
        float4 v0 = __ldg(f4 + (size_t)s0 * 32 + lane);
        float4 v1 = __ldg(f4 + (size_t)s1 * 32 + lane);
        float4 v2 = __ldg(f4 + (size_t)s2 * 32 + lane);
        float4 v3 = __ldg(f4 + (size_t)s3 * 32 + lane);
        acc.x += (v0.x + v1.x) + (v2.x + v3.x);
        acc.y += (v0.y + v1.y) + (v2.y + v3.y);
        acc.z += (v0.z + v1.z) + (v2.z + v3.z);
        acc.w += (v0.w + v1.w) + (v2.w + v3.w);
    }
    for (; e < end; e++) {
        float4 v = __ldg(f4 + (size_t)g_csr[e] * 32 + lane);
        acc.x += v.x; acc.y += v.y; acc.z += v.z; acc.w += v.w;
    }
    int c = end - beg;
    float w = 1.0f / (float)(c > 0 ? c : 1);
    acc.x *= w; acc.y *= w; acc.z *= w; acc.w *= w;
    bf16 hx = __float2bfloat16(acc.x), hy = __float2bfloat16(acc.y);
    bf16 hz = __float2bfloat16(acc.z), hw = __float2bfloat16(acc.w);
    union { bf162 b[2]; uint2 u; } H, L;
    H.b[0] = __halves2bfloat162(hx, hy);
    H.b[1] = __halves2bfloat162(hz, hw);
    L.b[0] = __halves2bfloat162(__float2bfloat16(acc.x - __bfloat162float(hx)),
                                __float2bfloat16(acc.y - __bfloat162float(hy)));
    L.b[1] = __halves2bfloat162(__float2bfloat16(acc.z - __bfloat162float(hz)),
                                __float2bfloat16(acc.w - __bfloat162float(hw)));
    uint2* o2 = reinterpret_cast<uint2*>(o) + (size_t)node * 64;   // 256 bf16 = 64 uint2
    o2[lane] = H.u;
    o2[32 + lane] = L.u;
}

// D=256 combined split in -> combined split out, 4-edge unroll
__global__ void gather_s2s_256(const bf16* __restrict__ f, bf16* __restrict__ o) {
    int node = (int)((blockIdx.x * (unsigned)blockDim.x + threadIdx.x) >> 5);
    if (node >= N_NODES) return;
    int lane = threadIdx.x & 31;
    int beg = g_rowptr[node], end = g_rowptr[node + 1];
    const uint4* f4 = reinterpret_cast<const uint4*>(f);   // 512 bf16 = 64 uint4/row
    float acc[8];
#pragma unroll
    for (int k = 0; k < 8; k++) acc[k] = 0.f;
    auto addrow = [&](uint4 H, uint4 L) {
        const uint32_t hs[4] = {H.x, H.y, H.z, H.w};
        const uint32_t ls[4] = {L.x, L.y, L.z, L.w};
#pragma unroll
        for (int k = 0; k < 4; k++) {
            bf162 hb = *reinterpret_cast<const bf162*>(&hs[k]);
            bf162 lb = *reinterpret_cast<const bf162*>(&ls[k]);
            acc[2 * k]     += __bfloat162float(hb.x) + __bfloat162float(lb.x);
            acc[2 * k + 1] += __bfloat162float(hb.y) + __bfloat162float(lb.y);
        }
    };
    int e = beg;
    for (; e + 4 <= end; e += 4) {
        int s0 = g_csr[e], s1 = g_csr[e + 1], s2 = g_csr[e + 2], s3 = g_csr[e + 3];
        uint4 H0 = __ldg(f4 + (size_t)s0 * 64 + lane);
        uint4 L0 = __ldg(f4 + (size_t)s0 * 64 + 32 + lane);
        uint4 H1 = __ldg(f4 + (size_t)s1 * 64 + lane);
        uint4 L1 = __ldg(f4 + (size_t)s1 * 64 + 32 + lane);
        uint4 H2 = __ldg(f4 + (size_t)s2 * 64 + lane);
        uint4 L2 = __ldg(f4 + (size_t)s2 * 64 + 32 + lane);
        uint4 H3 = __ldg(f4 + (size_t)s3 * 64 + lane);
        uint4 L3 = __ldg(f4 + (size_t)s3 * 64 + 32 + lane);
        addrow(H0, L0); addrow(H1, L1); addrow(H2, L2); addrow(H3, L3);
    }
    for (; e < end; e++) {
        int s = g_csr[e];
        addrow(__ldg(f4 + (size_t)s * 64 + lane), __ldg(f4 + (size_t)s * 64 + 32 + lane));
    }
    int c = end - beg;
    float w = 1.0f / (float)(c > 0 ? c : 1);
    union { bf162 b[4]; uint4 u; } H, L;
#pragma unroll
    for (int k = 0; k < 4; k++) {
        float v0 = acc[2 * k] * w, v1 = acc[2 * k + 1] * w;
        bf16 h0b = __float2bfloat16(v0), h1b = __float2bfloat16(v1);
        H.b[k] = __halves2bfloat162(h0b, h1b);
        L.b[k] = __halves2bfloat162(__float2bfloat16(v0 - __bfloat162float(h0b)),
                                    __float2bfloat16(v1 - __bfloat162float(h1b)));
    }
    uint4* o4 = reinterpret_cast<uint4*>(o) + (size_t)node * 64;
    o4[lane] = H.u;
    o4[32 + lane] = L.u;
}

// D=128 fp32 in -> out[node] += mean
__global__ void gather_add_128(const float* __restrict__ feat, float* __restrict__ out) {
    int node = (int)((blockIdx.x * (unsigned)blockDim.x + threadIdx.x) >> 5);
    if (node >= N_NODES) return;
    int lane = threadIdx.x & 31;
    int beg = g_rowptr[node], end = g_rowptr[node + 1];
    const float4* f4 = reinterpret_cast<const float4*>(feat);
    float4 acc = make_float4(0.f, 0.f, 0.f, 0.f);
    int e = beg;
    for (; e + 4 <= end; e += 4) {
        int s0 = g_csr[e], s1 = g_csr[e + 1], s2 = g_csr[e + 2], s3 = g_csr[e + 3];
        float4 v0 = __ldg(f4 + (size_t)s0 * 32 + lane);
        float4 v1 = __ldg(f4 + (size_t)s1 * 32 + lane);
        float4 v2 = __ldg(f4 + (size_t)s2 * 32 + lane);
        float4 v3 = __ldg(f4 + (size_t)s3 * 32 + lane);
        acc.x += (v0.x + v1.x) + (v2.x + v3.x);
        acc.y += (v0.y + v1.y) + (v2.y + v3.y);
        acc.z += (v0.z + v1.z) + (v2.z + v3.z);
        acc.w += (v0.w + v1.w) + (v2.w + v3.w);
    }
    for (; e < end; e++) {
        float4 v = __ldg(f4 + (size_t)g_csr[e] * 32 + lane);
        acc.x += v.x; acc.y += v.y; acc.z += v.z; acc.w += v.w;
    }
    int c = end - beg;
    float w = 1.0f / (float)(c > 0 ? c : 1);
    float4* o4 = reinterpret_cast<float4*>(out) + (size_t)node * 32 + lane;
    float4 o = *o4;
    o.x += acc.x * w; o.y += acc.y * w; o.z += acc.z * w; o.w += acc.w * w;
    *o4 = o;
}

// ---------------- tensor-core GEMM helpers ----------------
__device__ __forceinline__ uint32_t smem_u32(const void* p) {
    return (uint32_t)__cvta_generic_to_shared(p);
}
__device__ __forceinline__ void ldsm_x4(uint32_t* r, uint32_t a) {
    asm volatile("ldmatrix.sync.aligned.m8n8.x4.shared.b16 {%0,%1,%2,%3}, [%4];"
                 : "=r"(r[0]), "=r"(r[1]), "=r"(r[2]), "=r"(r[3]) : "r"(a));
}
__device__ __forceinline__ void ldsm_x4_t(uint32_t* r, uint32_t a) {
    asm volatile("ldmatrix.sync.aligned.m8n8.x4.trans.shared.b16 {%0,%1,%2,%3}, [%4];"
                 : "=r"(r[0]), "=r"(r[1]), "=r"(r[2]), "=r"(r[3]) : "r"(a));
}
__device__ __forceinline__ void mma16816(float* c, const uint32_t* a, const uint32_t* b) {
    asm volatile("mma.sync.aligned.m16n8k16.row.col.f32.bf16.bf16.f32 "
                 "{%0,%1,%2,%3}, {%4,%5,%6,%7}, {%8,%9}, {%0,%1,%2,%3};"
                 : "+f"(c[0]), "+f"(c[1]), "+f"(c[2]), "+f"(c[3])
                 : "r"(a[0]), "r"(a[1]), "r"(a[2]), "r"(a[3]),
                   "r"(b[0]), "r"(b[1]));
}
__device__ __forceinline__ void cp16(uint32_t dst, const void* src) {
    asm volatile("cp.async.ca.shared.global [%0], [%1], 16;" :: "r"(dst), "l"(src));
}
__device__ __forceinline__ void cp_commit() { asm volatile("cp.async.commit_group;"); }
__device__ __forceinline__ void cp_wait0()  { asm volatile("cp.async.wait_group 0;" ::: "memory"); }

// smem stage layout (bytes): A-hi 128x40, A-lo, W-hi 32x136, W-lo
#define ST_BYTES 37888
#define OFF_ALO  10240
#define OFF_WHI  20480
#define OFF_WLO  29184

// ---- fused dual-source pipelined tensor-core GEMM, fp32 via 3-term bf16 ----
// A sources use COMBINED split rows (stride 2K, lo at +K). All fills cp16,
// no bounds checks (rows padded to N_PAD). Output: combined split Cc
// (stride 2M, bias+relu) or routed fp32 (blockIdx.x==0 -> Cf0, ==1 -> Cf1+bias).
__global__ void __launch_bounds__(256, 2) gemm_tc(
    const bf16* __restrict__ A1,
    const bf16* __restrict__ W1hi, const bf16* __restrict__ W1lo,
    const bf16* __restrict__ A2,
    const bf16* __restrict__ W2hi, const bf16* __restrict__ W2lo,
    const float* __restrict__ bias,
    bf16* __restrict__ Cc, float* __restrict__ Cf0, float* __restrict__ Cf1,
    int Nrows, int K, int M, int do_relu)
{
    extern __shared__ __align__(16) char dynsmem[];
    const uint32_t sm0 = smem_u32(dynsmem);

    const int tid  = threadIdx.x;
    const int lane = tid & 31;
    const int warp = tid >> 5;
    const int wm = warp & 1;
    const int wn = warp >> 1;
    const int row0 = blockIdx.y * 128;
    const int col0 = blockIdx.x * 128;

    const bool dual = (A2 != nullptr);
    const int KT = K / 32;
    const int T  = (dual ? 2 : 1) * KT;

    float acc[4][4][4];
#pragma unroll
    for (int a = 0; a < 4; a++)
#pragma unroll
        for (int b = 0; b < 4; b++)
#pragma unroll
            for (int c = 0; c < 4; c++) acc[a][b][c] = 0.f;

    auto fill_async = [&](int t, int st) {
        int s_idx = t / KT;
        int k0 = (t - s_idx * KT) * 32;
        const bf16* A  = s_idx ? A2 : A1;
        const bf16* wh = s_idx ? W2hi : W1hi;
        const bf16* wl = s_idx ? W2lo : W1lo;
        uint32_t sbase = sm0 + st * ST_BYTES;
#pragma unroll
        for (int i = 0; i < 2; i++) {
            int chunk = tid + 256 * i;
            int r = chunk >> 4;
            int cc = (chunk & 15) * 8;
            uint32_t doff = (uint32_t)(r * 136 + cc) * 2;
            cp16(sbase + OFF_WHI + doff, wh + (size_t)(k0 + r) * M + col0 + cc);
            cp16(sbase + OFF_WLO + doff, wl + (size_t)(k0 + r) * M + col0 + cc);
        }
#pragma unroll
        for (int i = 0; i < 4; i++) {
            int idx = tid + 256 * i;          // 0..1023 chunks
            int r = idx >> 3, c = idx & 7;    // 128 rows x 8 chunks
            bool hp = (c < 4);
            int cc = (c & 3) * 8;             // col within 32
            uint32_t dst = sbase + (hp ? 0u : (uint32_t)OFF_ALO)
                           + (uint32_t)(r * 40 + cc) * 2;
            cp16(dst, A + (size_t)(row0 + r) * (2 * K) + (hp ? 0 : K) + k0 + cc);
        }
    };

    fill_async(0, 0);
    cp_commit();

    for (int t = 0; t < T; t++) {
        int st = t & 1;
        cp_wait0();
        __syncthreads();
        if (t + 1 < T) { fill_async(t + 1, 1 - st); cp_commit(); }

        uint32_t aBase = sm0 + st * ST_BYTES;
        uint32_t wBase = aBase + OFF_WHI;
#pragma unroll
        for (int ks = 0; ks < 32; ks += 16) {
            uint32_t ahi[4][4], alo[4][4];
#pragma unroll
            for (int mt = 0; mt < 4; mt++) {
                int r = wm * 64 + mt * 16 + (lane & 15);
                int c = ks + (lane >> 4) * 8;
                uint32_t off = (uint32_t)(r * 40 + c) * 2;
                ldsm_x4(ahi[mt], aBase + off);
                ldsm_x4(alo[mt], aBase + OFF_ALO + off);
            }
#pragma unroll
            for (int nt = 0; nt < 2; nt++) {
                int kr = ks + (lane & 15);
                int c  = wn * 32 + nt * 16 + (lane >> 4) * 8;
                uint32_t off = (uint32_t)(kr * 136 + c) * 2;
                uint32_t bhi[4], blo[4];
                ldsm_x4_t(bhi, wBase + off);
                ldsm_x4_t(blo, wBase + (OFF_WLO - OFF_WHI) + off);
#pragma unroll
                for (int mt = 0; mt < 4; mt++) {
#pragma unroll
                    for (int h = 0; h < 2; h++) {
                        float* cc = acc[mt][nt * 2 + h];
                        mma16816(cc, ahi[mt], &bhi[h * 2]);
                        mma16816(cc, alo[mt], &bhi[h * 2]);
                        mma16816(cc, ahi[mt], &blo[h * 2]);
                    }
                }
            }
        }
        __syncthreads();
    }

    // ---- epilogue ----
    const bool splitOut = (Cc != nullptr);
    float* Cf = (blockIdx.x == 0) ? Cf0 : Cf1;
    const bool useBias = bias && (splitOut || blockIdx.x == 1);
#pragma unroll
    for (int mt = 0; mt < 4; mt++) {
#pragma unroll
        for (int nt = 0; nt < 4; nt++) {
            int rg = row0 + wm * 64 + mt * 16 + (lane >> 2);
            int cg = col0 + wn * 32 + nt * 8 + (lane & 3) * 2;
            int cl = cg & 127;
            float b0v = 0.f, b1v = 0.f;
            if (useBias) {
                int bi = splitOut ? cg : cl;
                b0v = bias[bi]; b1v = bias[bi + 1];
            }
            float o0 = acc[mt][nt][0] + b0v;
            float o1 = acc[mt][nt][1] + b1v;
            float o2 = acc[mt][nt][2] + b0v;
            float o3 = acc[mt][nt][3] + b1v;
            if (do_relu) {
                o0 = fmaxf(o0, 0.f); o1 = fmaxf(o1, 0.f);
                o2 = fmaxf(o2, 0.f); o3 = fmaxf(o3, 0.f);
            }
#pragma unroll
            for (int hrow = 0; hrow < 2; hrow++) {
                int r = rg + hrow * 8;
                float p0 = hrow ? o2 : o0;
                float p1 = hrow ? o3 : o1;
                if (splitOut) {
                    // padded rows are safe to write; no guard
                    bf16 h0b = __float2bfloat16(p0), h1b = __float2bfloat16(p1);
                    bf16* base = Cc + (size_t)r * (2 * M) + cg;
                    *reinterpret_cast<bf162*>(base) = __halves2bfloat162(h0b, h1b);
                    *reinterpret_cast<bf162*>(base + M) =
                        __halves2bfloat162(__float2bfloat16(p0 - __bfloat162float(h0b)),
                                           __float2bfloat16(p1 - __bfloat162float(h1b)));
                } else if (r < Nrows) {
                    *reinterpret_cast<float2*>(Cf + (size_t)r * 128 + cl) =
                        make_float2(p0, p1);
                }
            }
        }
    }
}

// ---------------- launch ----------------
extern "C" void kernel_launch(void* const* d_in, const int* in_sizes, int n_in,
                              void* d_out, int out_size) {
    const float* x   = (const float*)d_in[0];
    const int*   ei  = (const int*)d_in[1];
    const float* Wl0 = (const float*)d_in[2];
    const float* b0  = (const float*)d_in[3];
    const float* Wr0 = (const float*)d_in[4];
    const float* Wl1 = (const float*)d_in[5];
    const float* b1  = (const float*)d_in[6];
    const float* Wr1 = (const float*)d_in[7];
    const float* Wl2 = (const float*)d_in[8];
    const float* b2  = (const float*)d_in[9];
    const float* Wr2 = (const float*)d_in[10];
    float* out = (float*)d_out;

    const int E = in_sizes[1] / 2;

    float *p2;
    bf16 *xs, *a0, *h0, *a1, *h1, *whi, *wlo;
    cudaGetSymbolAddress((void**)&p2,  g_p2);
    cudaGetSymbolAddress((void**)&xs,  g_x);
    cudaGetSymbolAddress((void**)&a0,  g_a0);
    cudaGetSymbolAddress((void**)&h0,  g_h0);
    cudaGetSymbolAddress((void**)&a1,  g_a1);
    cudaGetSymbolAddress((void**)&h1,  g_h1);
    cudaGetSymbolAddress((void**)&whi, g_whi);
    cudaGetSymbolAddress((void**)&wlo, g_wlo);

    static cudaStream_t s1 = nullptr;
    static cudaEvent_t evFork = nullptr, evJoin = nullptr;
    static int init_done = 0;
    if (!init_done) {
        cudaFuncSetAttribute(gemm_tc, cudaFuncAttributeMaxDynamicSharedMemorySize,
                             2 * ST_BYTES);
        cudaStreamCreateWithFlags(&s1, cudaStreamNonBlocking);
        cudaEventCreateWithFlags(&evFork, cudaEventDisableTiming);
        cudaEventCreateWithFlags(&evJoin, cudaEventDisableTiming);
        init_done = 1;
    }

    // ---- fork: splits on s1, CSR build + gather0 on the main stream ----
    cudaEventRecord(evFork, 0);
    cudaStreamWaitEvent(s1, evFork, 0);

    {
        int n4 = N_NODES * D_IN / 4;
        pack_split_x<<<(n4 + 255) / 256, 256, 0, s1>>>((const float4*)x, (bf162*)xs, n4);
    }
    auto splitw = [&](const float* s, int rows, int cols, int dstStride, int colOff,
                      int dstOff) {
        int n4 = rows * cols / 4;
        pack_split_w<<<(n4 + 255) / 256, 256, 0, s1>>>(
            (const float4*)s, (bf162*)(whi + dstOff), (bf162*)(wlo + dstOff),
            n4, cols / 4, dstStride, colOff);
    };
    splitw(Wl0, D_IN, D_H, D_H, 0, OFF_WL0);
    splitw(Wr0, D_IN, D_H, D_H, 0, OFF_WR0);
    splitw(Wl1, D_H, D_H, D_H, 0, OFF_WL1);
    splitw(Wr1, D_H, D_H, D_H, 0, OFF_WR1);
    splitw(Wl2, D_H, D_IN, 256, 0, OFF_W2P);
    splitw(Wr2, D_H, D_IN, 256, 128, OFF_W2P);
    cudaEventRecord(evJoin, s1);

    // main stream: CSR build
    detect_kernel<<<1, 32>>>(ei);
    zero_cc_kernel<<<(N_NODES + 1023) / 1024, 1024>>>();
    count_kernel<<<(E + 255) / 256, 256>>>(ei, E);
    scan1_kernel<<<SCAN_NBLK, 1024>>>();
    scan2_kernel<<<1, 32>>>(E);
    scan3_kernel<<<(N_NODES + 1023) / 1024, 1024>>>();
    fill_kernel<<<(E + 255) / 256, 256>>>(ei, E);

    const int gwarps = (N_NODES * 32 + 255) / 256;
    const dim3 gH(2, N_PAD / 128);            // 391 row-blocks, 2 col-blocks
    const int smem = 2 * ST_BYTES;

    // layer 0 gather (needs only CSR + x)
    gather_f2s_128<<<gwarps, 256>>>(x, a0);

    // join splits before first GEMM
    cudaStreamWaitEvent(0, evJoin, 0);

    gemm_tc<<<gH, 256, smem>>>(a0, whi + OFF_WL0, wlo + OFF_WL0,
                               xs, whi + OFF_WR0, wlo + OFF_WR0,
                               b0, h0, nullptr, nullptr, N_NODES, D_IN, D_H, 1);
    // layer 1
    gather_s2s_256<<<gwarps, 256>>>(h0, a1);
    gemm_tc<<<gH, 256, smem>>>(a1, whi + OFF_WL1, wlo + OFF_WL1,
                               h0, whi + OFF_WR1, wlo + OFF_WR1,
                               b1, h1, nullptr, nullptr, N_NODES, D_H, D_H, 1);
    // layer 2: packed [Wl2|Wr2]; block.x=0 -> p2, 1 -> out(+b2)
    gemm_tc<<<gH, 256, smem>>>(h1, whi + OFF_W2P, wlo + OFF_W2P,
                               nullptr, nullptr, nullptr,
                               b2, nullptr, p2, out, N_NODES, D_H, 256, 0);
    gather_add_128<<<gwarps, 256>>>(p2, out);
}